// round 6
// baseline (speedup 1.0000x reference)
#include <cuda_runtime.h>

// GCN, 4 layers: h' = relu( D^-1/2 (A+I) D^-1/2 (h W) + b )
// g = (h@W)*dinv[row];  agg[d] = g[d] + sum_{(s->d)} g[s]  (raw, via CSR gather)
// relu(agg*dinv + b) of layer l fused into layer l+1's A-tile load.

#define NN 100000
#define EE 500000
#define FD 128

__device__ float g_dinv[NN];
__device__ float g_g[(size_t)NN * FD];
__device__ float g_agg[(size_t)NN * FD];
// CSR (dst-major) scratch
__device__ int g_cnt[NN];
__device__ int g_rowptr[NN + 1];
__device__ int g_fill[NN];
__device__ int g_eidx[EE];
__device__ int g_bsums[256];

// ---------------- degree + CSR build ----------------

__global__ void k_zero_cnt(int n) {
  int i = blockIdx.x * blockDim.x + threadIdx.x;
  if (i < n) g_cnt[i] = 0;
}
__global__ void k_count(const int* __restrict__ dst, int e) {
  int i = blockIdx.x * blockDim.x + threadIdx.x;
  if (i < e) atomicAdd(&g_cnt[dst[i]], 1);
}
__global__ void k_deg_rsqrt(int n) {
  int i = blockIdx.x * blockDim.x + threadIdx.x;
  if (i < n) g_dinv[i] = rsqrtf((float)(1 + g_cnt[i]));  // +1 self loop
}

#define SCAN_B 512
__global__ void k_scan1(int n) {  // per-block inclusive scan of g_cnt -> rowptr[i+1]
  __shared__ int sm[SCAN_B];
  int i = blockIdx.x * SCAN_B + threadIdx.x;
  sm[threadIdx.x] = (i < n) ? g_cnt[i] : 0;
  __syncthreads();
  for (int off = 1; off < SCAN_B; off <<= 1) {
    int t = (threadIdx.x >= off) ? sm[threadIdx.x - off] : 0;
    __syncthreads();
    sm[threadIdx.x] += t;
    __syncthreads();
  }
  if (i < n) g_rowptr[i + 1] = sm[threadIdx.x];
  if (threadIdx.x == SCAN_B - 1) g_bsums[blockIdx.x] = sm[threadIdx.x];
  if (i == 0) g_rowptr[0] = 0;
}
__global__ void k_scan2(int nb) {  // single block (256 threads) scan of block sums
  __shared__ int sm[256];
  sm[threadIdx.x] = (threadIdx.x < nb) ? g_bsums[threadIdx.x] : 0;
  __syncthreads();
  for (int off = 1; off < 256; off <<= 1) {
    int t = (threadIdx.x >= off) ? sm[threadIdx.x - off] : 0;
    __syncthreads();
    sm[threadIdx.x] += t;
    __syncthreads();
  }
  if (threadIdx.x < nb) g_bsums[threadIdx.x] = sm[threadIdx.x];
}
__global__ void k_scan3(int n) {  // add block offsets; init g_fill
  int i = blockIdx.x * SCAN_B + threadIdx.x;
  if (i < n) {
    if (blockIdx.x > 0) g_rowptr[i + 1] += g_bsums[blockIdx.x - 1];
    int base = (blockIdx.x > 0) ? g_bsums[blockIdx.x - 1] : 0;
    // g_fill[i] = exclusive scan value = rowptr[i]; rowptr[i] not all written yet
    // within this grid, so recompute: rowptr[i] = inclusive[i-1]+base handled by
    // a separate pass below instead.
    (void)base;
  }
}
__global__ void k_fill_init(int n) {
  int i = blockIdx.x * blockDim.x + threadIdx.x;
  if (i < n) g_fill[i] = g_rowptr[i];
}
__global__ void k_fill(const int* __restrict__ src, const int* __restrict__ dst,
                       int e) {
  int i = blockIdx.x * blockDim.x + threadIdx.x;
  if (i < e) {
    int p = atomicAdd(&g_fill[dst[i]], 1);
    g_eidx[p] = src[i];
  }
}

// ---------------- wide GEMM: 128x128 tile, 128 thr, 8x16/thread, f32x2 FMA ----
// A:[M,128], B:[128,128]. g = (A'@B)*dinv[row] -> g_g.
// FUSE: A' = relu(A*dinv[row] + bias[k]) applied on load.

template <bool FUSE>
__global__ __launch_bounds__(128, 2)
void k_gemm_wide(const float* __restrict__ A, const float* __restrict__ B,
                 const float* __restrict__ bias, int M) {
  __shared__ float As[2][8][128];
  __shared__ float Bs[2][8][128];

  const int tid = threadIdx.x;
  const int bm  = blockIdx.x * 128;
  const int tx  = tid & 7;    // 8 col groups of 16
  const int ty  = tid >> 3;   // 16 row groups of 8

  // A loader: thread tid owns row (bm+tid), loads its 8 k-values per chunk.
  const int arow = bm + tid;
  const bool aIn = arow < M;
  const float sA = aIn ? g_dinv[arow] : 0.0f;
  const float* Aptr = A + (size_t)arow * 128;
  // B loader: 2 float4 per thread: row tid>>4 (0..7), cols (tid&15)*8 .. +7
  const int bRow = tid >> 4;
  const int bCol = (tid & 15) * 8;
  const float4 zero4 = make_float4(0.f, 0.f, 0.f, 0.f);

  unsigned long long acc[8][8];
#pragma unroll
  for (int i = 0; i < 8; i++)
#pragma unroll
    for (int j = 0; j < 8; j++) acc[i][j] = 0ull;

#define LOAD_AB(k0, av0, av1, bv0, bv1)                               \
  do {                                                                \
    av0 = aIn ? *(const float4*)(Aptr + (k0)) : zero4;                \
    av1 = aIn ? *(const float4*)(Aptr + (k0) + 4) : zero4;            \
    if (FUSE && aIn) {                                                \
      float4 c0 = *(const float4*)(bias + (k0));                      \
      float4 c1 = *(const float4*)(bias + (k0) + 4);                  \
      av0.x = fmaxf(av0.x * sA + c0.x, 0.f);                          \
      av0.y = fmaxf(av0.y * sA + c0.y, 0.f);                          \
      av0.z = fmaxf(av0.z * sA + c0.z, 0.f);                          \
      av0.w = fmaxf(av0.w * sA + c0.w, 0.f);                          \
      av1.x = fmaxf(av1.x * sA + c1.x, 0.f);                          \
      av1.y = fmaxf(av1.y * sA + c1.y, 0.f);                          \
      av1.z = fmaxf(av1.z * sA + c1.z, 0.f);                          \
      av1.w = fmaxf(av1.w * sA + c1.w, 0.f);                          \
    }                                                                 \
    bv0 = *(const float4*)(B + (size_t)((k0) + bRow) * 128 + bCol);   \
    bv1 = *(const float4*)(B + (size_t)((k0) + bRow) * 128 + bCol + 4);\
  } while (0)

#define STORE_AB(bi, av0, av1, bv0, bv1)                              \
  do {                                                                \
    As[bi][0][tid] = av0.x; As[bi][1][tid] = av0.y;                   \
    As[bi][2][tid] = av0.z; As[bi][3][tid] = av0.w;                   \
    As[bi][4][tid] = av1.x; As[bi][5][tid] = av1.y;                   \
    As[bi][6][tid] = av1.z; As[bi][7][tid] = av1.w;                   \
    *(float4*)&Bs[bi][bRow][bCol]     = bv0;                          \
    *(float4*)&Bs[bi][bRow][bCol + 4] = bv1;                          \
  } while (0)

  {
    float4 av0, av1, bv0, bv1;
    LOAD_AB(0, av0, av1, bv0, bv1);
    STORE_AB(0, av0, av1, bv0, bv1);
  }
  __syncthreads();

  int buf = 0;
  for (int k0 = 8; k0 <= 128; k0 += 8) {
    float4 av0, av1, bv0, bv1;
    if (k0 < 128) LOAD_AB(k0, av0, av1, bv0, bv1);
    // compute on buf
#pragma unroll
    for (int kk = 0; kk < 8; kk++) {
      float a[8];
      *(float4*)(a)     = *(const float4*)&As[buf][kk][ty * 8];
      *(float4*)(a + 4) = *(const float4*)&As[buf][kk][ty * 8 + 4];
      unsigned long long bb[8];
      *(ulonglong2*)(bb)     = *(const ulonglong2*)&Bs[buf][kk][tx * 16];
      *(ulonglong2*)(bb + 2) = *(const ulonglong2*)&Bs[buf][kk][tx * 16 + 4];
      *(ulonglong2*)(bb + 4) = *(const ulonglong2*)&Bs[buf][kk][tx * 16 + 8];
      *(ulonglong2*)(bb + 6) = *(const ulonglong2*)&Bs[buf][kk][tx * 16 + 12];
#pragma unroll
      for (int i = 0; i < 8; i++) {
        unsigned long long a2;
        asm("mov.b64 %0, {%1, %1};" : "=l"(a2) : "f"(a[i]));
#pragma unroll
        for (int j = 0; j < 8; j++)
          asm("fma.rn.f32x2 %0, %1, %2, %0;"
              : "+l"(acc[i][j]) : "l"(a2), "l"(bb[j]));
      }
    }
    if (k0 < 128) {
      STORE_AB(buf ^ 1, av0, av1, bv0, bv1);
      __syncthreads();
      buf ^= 1;
    }
  }
#undef LOAD_AB
#undef STORE_AB

  // epilogue: g = acc * dinv[row]
#pragma unroll
  for (int i = 0; i < 8; i++) {
    int r = bm + ty * 8 + i;
    if (r >= M) continue;
    float s = g_dinv[r];
    float* out = g_g + (size_t)r * 128 + tx * 16;
#pragma unroll
    for (int j = 0; j < 8; j += 2) {
      float x0, x1, x2, x3;
      asm("mov.b64 {%0, %1}, %2;" : "=f"(x0), "=f"(x1) : "l"(acc[i][j]));
      asm("mov.b64 {%0, %1}, %2;" : "=f"(x2), "=f"(x3) : "l"(acc[i][j + 1]));
      *(float4*)(out + j * 2) = make_float4(x0 * s, x1 * s, x2 * s, x3 * s);
    }
  }
}

// ---------------- narrow GEMM (D=40, TN=64): as R4, single store ----------------

__global__ __launch_bounds__(256, 2)
void k_gemm_narrow(const float* __restrict__ A, const float* __restrict__ B,
                   const float* __restrict__ bias, int M, int D) {
  constexpr int TN = 64;
  __shared__ float As[2][8][128];
  __shared__ float Bs[2][8][TN];

  const int tid = threadIdx.x;
  const int bm  = blockIdx.x * 128;
  const int tx  = tid & 15;
  const int ty  = tid >> 4;

  const int aRow = tid >> 1;
  const int aCol = (tid & 1) * 4;
  const int arow = bm + aRow;
  const bool aIn = arow < M;
  const float sA = aIn ? g_dinv[arow] : 0.0f;
  const float* Aptr = A + (size_t)arow * 128 + aCol;

  const int bRow = tid / (TN / 4);
  const int bCol = (tid % (TN / 4)) * 4;
  const bool bThread = tid < 2 * TN;
  const bool bIn = bThread && (bCol < D);

  unsigned long long acc[8][2];
#pragma unroll
  for (int i = 0; i < 8; i++) { acc[i][0] = 0ull; acc[i][1] = 0ull; }

  const float4 zero4 = make_float4(0.f, 0.f, 0.f, 0.f);

#define NLOAD_A(k0, av)                                             \
  do {                                                              \
    av = aIn ? *(const float4*)(Aptr + (k0)) : zero4;               \
    float4 c = aIn ? *(const float4*)(bias + (k0) + aCol) : zero4;  \
    av.x = fmaxf(av.x * sA + c.x, 0.f);                             \
    av.y = fmaxf(av.y * sA + c.y, 0.f);                             \
    av.z = fmaxf(av.z * sA + c.z, 0.f);                             \
    av.w = fmaxf(av.w * sA + c.w, 0.f);                             \
  } while (0)

#define NSTORE(bi, av, bv)                                          \
  do {                                                              \
    As[bi][aCol + 0][aRow] = av.x;                                  \
    As[bi][aCol + 1][aRow] = av.y;                                  \
    As[bi][aCol + 2][aRow] = av.z;                                  \
    As[bi][aCol + 3][aRow] = av.w;                                  \
    if (bThread) *(float4*)&Bs[bi][bRow][bCol] = bv;                \
  } while (0)

  {
    float4 av, bv;
    NLOAD_A(0, av);
    bv = bIn ? *(const float4*)(B + (size_t)bRow * D + bCol) : zero4;
    NSTORE(0, av, bv);
  }
  __syncthreads();

  int buf = 0;
  for (int k0 = 8; k0 <= 128; k0 += 8) {
    float4 av, bv;
    if (k0 < 128) {
      NLOAD_A(k0, av);
      bv = bIn ? *(const float4*)(B + (size_t)(k0 + bRow) * D + bCol) : zero4;
    }
#pragma unroll
    for (int kk = 0; kk < 8; kk++) {
      float a[8];
      *(float4*)(a)     = *(const float4*)&As[buf][kk][ty * 8];
      *(float4*)(a + 4) = *(const float4*)&As[buf][kk][ty * 8 + 4];
      ulonglong2 bb = *(const ulonglong2*)&Bs[buf][kk][tx * 4];
#pragma unroll
      for (int i = 0; i < 8; i++) {
        unsigned long long a2;
        asm("mov.b64 %0, {%1, %1};" : "=l"(a2) : "f"(a[i]));
        asm("fma.rn.f32x2 %0, %1, %2, %0;" : "+l"(acc[i][0]) : "l"(a2), "l"(bb.x));
        asm("fma.rn.f32x2 %0, %1, %2, %0;" : "+l"(acc[i][1]) : "l"(a2), "l"(bb.y));
      }
    }
    if (k0 < 128) {
      NSTORE(buf ^ 1, av, bv);
      __syncthreads();
      buf ^= 1;
    }
  }
#undef NLOAD_A
#undef NSTORE

#pragma unroll
  for (int i = 0; i < 8; i++) {
    int r = bm + ty * 8 + i;
    if (r >= M) continue;
    int col = tx * 4;
    if (col >= D) continue;
    float s = g_dinv[r];
    float x0, x1, x2, x3;
    asm("mov.b64 {%0, %1}, %2;" : "=f"(x0), "=f"(x1) : "l"(acc[i][0]));
    asm("mov.b64 {%0, %1}, %2;" : "=f"(x2), "=f"(x3) : "l"(acc[i][1]));
    *(float4*)(g_g + (size_t)r * D + col) =
        make_float4(x0 * s, x1 * s, x2 * s, x3 * s);
  }
}

// ---------------- CSR gather aggregation: agg[d] = g[d] + sum g[src] ----------

__global__ void k_gather(int n) {  // D = 128, warp per node
  int w    = (blockIdx.x * blockDim.x + threadIdx.x) >> 5;
  int lane = threadIdx.x & 31;
  if (w >= n) return;
  int beg = __ldg(g_rowptr + w);
  int end = __ldg(g_rowptr + w + 1);
  float4 acc = *(const float4*)(g_g + (size_t)w * 128 + lane * 4);
  for (int e = beg; e < end; e++) {
    int s = __ldg(g_eidx + e);
    float4 v = *(const float4*)(g_g + (size_t)s * 128 + lane * 4);
    acc.x += v.x; acc.y += v.y; acc.z += v.z; acc.w += v.w;
  }
  *(float4*)(g_agg + (size_t)w * 128 + lane * 4) = acc;
}

__global__ void k_gather_narrow(int n, int D) {  // D = 40, lanes 0..9 active
  int w    = (blockIdx.x * blockDim.x + threadIdx.x) >> 5;
  int lane = threadIdx.x & 31;
  if (w >= n) return;
  int c = lane * 4;
  if (c >= D) return;
  int beg = __ldg(g_rowptr + w);
  int end = __ldg(g_rowptr + w + 1);
  float4 acc = *(const float4*)(g_g + (size_t)w * D + c);
  for (int e = beg; e < end; e++) {
    int s = __ldg(g_eidx + e);
    float4 v = *(const float4*)(g_g + (size_t)s * D + c);
    acc.x += v.x; acc.y += v.y; acc.z += v.z; acc.w += v.w;
  }
  *(float4*)(g_agg + (size_t)w * D + c) = acc;
}

// ---------------- final output: out = agg * dinv + b ----------------

__global__ void k_finalize(const float* __restrict__ bias, float* __restrict__ out,
                           int M, int D) {
  int per_row = D >> 2;
  int t = blockIdx.x * blockDim.x + threadIdx.x;
  if (t >= M * per_row) return;
  int row = t / per_row;
  int c4  = t - row * per_row;
  size_t off = (size_t)row * D + (size_t)c4 * 4;
  float s = g_dinv[row];
  float4 v = *(const float4*)(g_agg + off);
  float4 b = *(const float4*)(bias + c4 * 4);
  v.x = v.x * s + b.x;
  v.y = v.y * s + b.y;
  v.z = v.z * s + b.z;
  v.w = v.w * s + b.w;
  *(float4*)(out + off) = v;
}

// ---------------- host launcher ----------------

extern "C" void kernel_launch(void* const* d_in, const int* in_sizes, int n_in,
                              void* d_out, int out_size) {
  const float* x  = (const float*)d_in[0];
  const int*   ei = (const int*)d_in[1];
  const float* W[4] = {(const float*)d_in[2], (const float*)d_in[4],
                       (const float*)d_in[6], (const float*)d_in[8]};
  const float* b[4] = {(const float*)d_in[3], (const float*)d_in[5],
                       (const float*)d_in[7], (const float*)d_in[9]};

  int M = in_sizes[0] / FD;  // 100000
  int E = in_sizes[1] / 2;   // 500000
  const int* src = ei;
  const int* dst = ei + E;

  float* agg;
  cudaGetSymbolAddress((void**)&agg, g_agg);

  // degree + CSR build
  int nscan = (M + SCAN_B - 1) / SCAN_B;  // 196
  k_zero_cnt<<<(M + 255) / 256, 256>>>(M);
  k_count<<<(E + 255) / 256, 256>>>(dst, E);
  k_deg_rsqrt<<<(M + 255) / 256, 256>>>(M);
  k_scan1<<<nscan, SCAN_B>>>(M);
  k_scan2<<<1, 256>>>(nscan);
  k_scan3<<<nscan, SCAN_B>>>(M);
  k_fill_init<<<(M + 255) / 256, 256>>>(M);
  k_fill<<<(E + 255) / 256, 256>>>(src, dst, E);

  int GB = (M + 127) / 128;                // 782
  int gatherB = (M * 32 + 255) / 256;      // 12500

  // layer 0
  k_gemm_wide<false><<<GB, 128>>>(x, W[0], b[0], M);
  k_gather<<<gatherB, 256>>>(M);
  // layers 1-2 (finalize fused into A load)
  k_gemm_wide<true><<<GB, 128>>>(agg, W[1], b[0], M);
  k_gather<<<gatherB, 256>>>(M);
  k_gemm_wide<true><<<GB, 128>>>(agg, W[2], b[1], M);
  k_gather<<<gatherB, 256>>>(M);
  // layer 3: D = 40
  k_gemm_narrow<<<GB, 256>>>(agg, W[3], b[2], M, 40);
  k_gather_narrow<<<gatherB, 256>>>(M, 40);
  k_finalize<<<(M * 10 + 255) / 256, 256>>>(b[3], (float*)d_out, M, 40);
}

// round 8
// speedup vs baseline: 1.2096x; 1.2096x over previous
#include <cuda_runtime.h>
#include <cstdint>

// GCN, 4 layers: h' = relu( D^-1/2 (A+I) D^-1/2 (h W) + b )
// g = (h@W)*dinv[row]  (GEMM, FFMA2 with A pre-duplicated in smem)
// agg[d] = g[d] + sum_{(s->d)} g[s]   (CSR gather, one write per node)
// relu(agg*dinv + b) of layer l fused into layer l+1's A-tile load.

#define NN 100000
#define EE 500000
#define FD 128

__device__ float g_dinv[NN];
__device__ float g_g[(size_t)NN * FD];
__device__ float g_agg[(size_t)NN * FD];
// CSR (dst-major)
__device__ int g_cnt[NN];
__device__ int g_rowptr[NN + 1];
__device__ int g_fill[NN];
__device__ int g_eidx[EE];
__device__ int g_bsums[256];

// ---------------- degree + CSR build ----------------

__global__ void k_zero_cnt(int n) {
  int i = blockIdx.x * blockDim.x + threadIdx.x;
  if (i < n) g_cnt[i] = 0;
}
__global__ void k_count(const int* __restrict__ dst, int e) {
  int i = blockIdx.x * blockDim.x + threadIdx.x;
  if (i < e) atomicAdd(&g_cnt[dst[i]], 1);
}
__global__ void k_deg_rsqrt(int n) {
  int i = blockIdx.x * blockDim.x + threadIdx.x;
  if (i < n) g_dinv[i] = rsqrtf((float)(1 + g_cnt[i]));  // +1 self loop
}

#define SCAN_B 512
__global__ void k_scan1(int n) {  // block-local inclusive scan -> rowptr[i+1]
  __shared__ int sm[SCAN_B];
  int i = blockIdx.x * SCAN_B + threadIdx.x;
  sm[threadIdx.x] = (i < n) ? g_cnt[i] : 0;
  __syncthreads();
  for (int off = 1; off < SCAN_B; off <<= 1) {
    int t = (threadIdx.x >= off) ? sm[threadIdx.x - off] : 0;
    __syncthreads();
    sm[threadIdx.x] += t;
    __syncthreads();
  }
  if (i < n) g_rowptr[i + 1] = sm[threadIdx.x];
  if (threadIdx.x == SCAN_B - 1) g_bsums[blockIdx.x] = sm[threadIdx.x];
  if (i == 0) g_rowptr[0] = 0;
}
__global__ void k_scan2(int nb) {  // single-block scan of block sums
  __shared__ int sm[256];
  sm[threadIdx.x] = (threadIdx.x < nb) ? g_bsums[threadIdx.x] : 0;
  __syncthreads();
  for (int off = 1; off < 256; off <<= 1) {
    int t = (threadIdx.x >= off) ? sm[threadIdx.x - off] : 0;
    __syncthreads();
    sm[threadIdx.x] += t;
    __syncthreads();
  }
  if (threadIdx.x < nb) g_bsums[threadIdx.x] = sm[threadIdx.x];
}
__global__ void k_scan3(int n) {  // add carried block offsets
  int i = blockIdx.x * SCAN_B + threadIdx.x;
  if (i < n && blockIdx.x > 0) g_rowptr[i + 1] += g_bsums[blockIdx.x - 1];
}
__global__ void k_fill_init(int n) {
  int i = blockIdx.x * blockDim.x + threadIdx.x;
  if (i < n) g_fill[i] = g_rowptr[i];
}
__global__ void k_fill(const int* __restrict__ src, const int* __restrict__ dst,
                       int e) {
  int i = blockIdx.x * blockDim.x + threadIdx.x;
  if (i < e) {
    int p = atomicAdd(&g_fill[dst[i]], 1);
    g_eidx[p] = src[i];
  }
}

// ---------------- wide GEMM (128x128 tile, 256 thr, 8x8 f32x2/thread) --------
// A duplicated in smem: As2[k][row] = (a, a) so FFMA2 consumes LDS directly
// (no mov.b64 dup in the inner loop).  B pairs are natural float layout.
// FUSE: A' = relu(A*dinv[row] + bias[k]) applied on load.

template <bool FUSE>
__global__ __launch_bounds__(256, 2)
void k_gemm_wide(const float* __restrict__ A, const float* __restrict__ B,
                 const float* __restrict__ bias, int M) {
  __shared__ float2 As2[2][8][128];  // 8 KB per buffer (dup pairs)
  __shared__ float  Bs[2][8][128];   // 4 KB per buffer

  const int tid = threadIdx.x;
  const int bm  = blockIdx.x * 128;
  const int tx  = tid & 15;   // 16 col groups of 8
  const int ty  = tid >> 4;   // 16 row groups of 8

  // A loader: thread owns (row = tid>>1, k-quad = (tid&1)*4)
  const int aRow = tid >> 1;
  const int aCol = (tid & 1) * 4;
  const int arow = bm + aRow;
  const bool aIn = arow < M;
  const float sA = aIn ? g_dinv[arow] : 0.0f;
  const float* Aptr = A + (size_t)arow * 128 + aCol;

  // B loader: row = tid>>5 (0..7), cols (tid&31)*4
  const int bRow = tid >> 5;
  const int bCol = (tid & 31) * 4;

  unsigned long long acc[8][4];
#pragma unroll
  for (int i = 0; i < 8; i++)
#pragma unroll
    for (int j = 0; j < 4; j++) acc[i][j] = 0ull;

  const float4 zero4 = make_float4(0.f, 0.f, 0.f, 0.f);

#define LOAD_A(k0, av)                                              \
  do {                                                              \
    av = aIn ? *(const float4*)(Aptr + (k0)) : zero4;               \
    if (FUSE && aIn) {                                              \
      float4 c = *(const float4*)(bias + (k0) + aCol);              \
      av.x = fmaxf(av.x * sA + c.x, 0.f);                           \
      av.y = fmaxf(av.y * sA + c.y, 0.f);                           \
      av.z = fmaxf(av.z * sA + c.z, 0.f);                           \
      av.w = fmaxf(av.w * sA + c.w, 0.f);                           \
    }                                                               \
  } while (0)

#define STORE_TILES(bi, av, bv)                                     \
  do {                                                              \
    As2[bi][aCol + 0][aRow] = make_float2(av.x, av.x);              \
    As2[bi][aCol + 1][aRow] = make_float2(av.y, av.y);              \
    As2[bi][aCol + 2][aRow] = make_float2(av.z, av.z);              \
    As2[bi][aCol + 3][aRow] = make_float2(av.w, av.w);              \
    *(float4*)&Bs[bi][bRow][bCol] = bv;                             \
  } while (0)

  {
    float4 av, bv;
    LOAD_A(0, av);
    bv = *(const float4*)(B + (size_t)bRow * 128 + bCol);
    STORE_TILES(0, av, bv);
  }
  __syncthreads();

  int buf = 0;
  for (int k0 = 8; k0 <= 128; k0 += 8) {
    float4 av, bv;
    if (k0 < 128) {
      LOAD_A(k0, av);
      bv = *(const float4*)(B + (size_t)(k0 + bRow) * 128 + bCol);
    }
#pragma unroll
    for (int kk = 0; kk < 8; kk++) {
      unsigned long long a2[8];
      *(ulonglong2*)(a2)     = *(const ulonglong2*)&As2[buf][kk][ty * 8];
      *(ulonglong2*)(a2 + 2) = *(const ulonglong2*)&As2[buf][kk][ty * 8 + 2];
      *(ulonglong2*)(a2 + 4) = *(const ulonglong2*)&As2[buf][kk][ty * 8 + 4];
      *(ulonglong2*)(a2 + 6) = *(const ulonglong2*)&As2[buf][kk][ty * 8 + 6];
      unsigned long long bb[4];
      *(ulonglong2*)(bb)     = *(const ulonglong2*)&Bs[buf][kk][tx * 8];
      *(ulonglong2*)(bb + 2) = *(const ulonglong2*)&Bs[buf][kk][tx * 8 + 4];
#pragma unroll
      for (int i = 0; i < 8; i++)
#pragma unroll
        for (int j = 0; j < 4; j++)
          asm("fma.rn.f32x2 %0, %1, %2, %0;"
              : "+l"(acc[i][j]) : "l"(a2[i]), "l"(bb[j]));
    }
    if (k0 < 128) {
      STORE_TILES(buf ^ 1, av, bv);
      __syncthreads();
      buf ^= 1;
    }
  }
#undef LOAD_A
#undef STORE_TILES

  // epilogue: g = acc * dinv[row]  (single store; gather handles self term)
#pragma unroll
  for (int i = 0; i < 8; i++) {
    int r = bm + ty * 8 + i;
    if (r >= M) continue;
    float s = g_dinv[r];
    float* out = g_g + (size_t)r * 128 + tx * 8;
#pragma unroll
    for (int j = 0; j < 4; j += 2) {
      float x0, x1, x2, x3;
      asm("mov.b64 {%0, %1}, %2;" : "=f"(x0), "=f"(x1) : "l"(acc[i][j]));
      asm("mov.b64 {%0, %1}, %2;" : "=f"(x2), "=f"(x3) : "l"(acc[i][j + 1]));
      *(float4*)(out + j * 2) = make_float4(x0 * s, x1 * s, x2 * s, x3 * s);
    }
  }
}

// ---------------- narrow GEMM (D=40, TN=64, FFMA2) ----------------

__global__ __launch_bounds__(256, 2)
void k_gemm_narrow(const float* __restrict__ A, const float* __restrict__ B,
                   const float* __restrict__ bias, int M, int D) {
  constexpr int TN = 64;
  __shared__ float As[2][8][128];
  __shared__ float Bs[2][8][TN];

  const int tid = threadIdx.x;
  const int bm  = blockIdx.x * 128;
  const int tx  = tid & 15;
  const int ty  = tid >> 4;

  const int aRow = tid >> 1;
  const int aCol = (tid & 1) * 4;
  const int arow = bm + aRow;
  const bool aIn = arow < M;
  const float sA = aIn ? g_dinv[arow] : 0.0f;
  const float* Aptr = A + (size_t)arow * 128 + aCol;

  const int bRow = tid / (TN / 4);
  const int bCol = (tid % (TN / 4)) * 4;
  const bool bThread = tid < 2 * TN;
  const bool bIn = bThread && (bCol < D);

  unsigned long long acc[8][2];
#pragma unroll
  for (int i = 0; i < 8; i++) { acc[i][0] = 0ull; acc[i][1] = 0ull; }

  const float4 zero4 = make_float4(0.f, 0.f, 0.f, 0.f);

#define NLOAD_A(k0, av)                                             \
  do {                                                              \
    av = aIn ? *(const float4*)(Aptr + (k0)) : zero4;               \
    float4 c = aIn ? *(const float4*)(bias + (k0) + aCol) : zero4;  \
    av.x = fmaxf(av.x * sA + c.x, 0.f);                             \
    av.y = fmaxf(av.y * sA + c.y, 0.f);                             \
    av.z = fmaxf(av.z * sA + c.z, 0.f);                             \
    av.w = fmaxf(av.w * sA + c.w, 0.f);                             \
  } while (0)

#define NSTORE(bi, av, bv)                                          \
  do {                                                              \
    As[bi][aCol + 0][aRow] = av.x;                                  \
    As[bi][aCol + 1][aRow] = av.y;                                  \
    As[bi][aCol + 2][aRow] = av.z;                                  \
    As[bi][aCol + 3][aRow] = av.w;                                  \
    if (bThread) *(float4*)&Bs[bi][bRow][bCol] = bv;                \
  } while (0)

  {
    float4 av, bv;
    NLOAD_A(0, av);
    bv = bIn ? *(const float4*)(B + (size_t)bRow * D + bCol) : zero4;
    NSTORE(0, av, bv);
  }
  __syncthreads();

  int buf = 0;
  for (int k0 = 8; k0 <= 128; k0 += 8) {
    float4 av, bv;
    if (k0 < 128) {
      NLOAD_A(k0, av);
      bv = bIn ? *(const float4*)(B + (size_t)(k0 + bRow) * D + bCol) : zero4;
    }
#pragma unroll
    for (int kk = 0; kk < 8; kk++) {
      float a[8];
      *(float4*)(a)     = *(const float4*)&As[buf][kk][ty * 8];
      *(float4*)(a + 4) = *(const float4*)&As[buf][kk][ty * 8 + 4];
      ulonglong2 bb = *(const ulonglong2*)&Bs[buf][kk][tx * 4];
#pragma unroll
      for (int i = 0; i < 8; i++) {
        unsigned long long a2;
        asm("mov.b64 %0, {%1, %1};" : "=l"(a2) : "f"(a[i]));
        asm("fma.rn.f32x2 %0, %1, %2, %0;" : "+l"(acc[i][0]) : "l"(a2), "l"(bb.x));
        asm("fma.rn.f32x2 %0, %1, %2, %0;" : "+l"(acc[i][1]) : "l"(a2), "l"(bb.y));
      }
    }
    if (k0 < 128) {
      NSTORE(buf ^ 1, av, bv);
      __syncthreads();
      buf ^= 1;
    }
  }
#undef NLOAD_A
#undef NSTORE

#pragma unroll
  for (int i = 0; i < 8; i++) {
    int r = bm + ty * 8 + i;
    if (r >= M) continue;
    int col = tx * 4;
    if (col >= D) continue;
    float s = g_dinv[r];
    float x0, x1, x2, x3;
    asm("mov.b64 {%0, %1}, %2;" : "=f"(x0), "=f"(x1) : "l"(acc[i][0]));
    asm("mov.b64 {%0, %1}, %2;" : "=f"(x2), "=f"(x3) : "l"(acc[i][1]));
    *(float4*)(g_g + (size_t)r * D + col) =
        make_float4(x0 * s, x1 * s, x2 * s, x3 * s);
  }
}

// ---------------- CSR gather: agg[d] = g[d] + sum g[src] ----------------

__global__ void k_gather(int n) {  // D = 128, warp per node
  int w    = (blockIdx.x * blockDim.x + threadIdx.x) >> 5;
  int lane = threadIdx.x & 31;
  if (w >= n) return;
  int beg = __ldg(g_rowptr + w);
  int end = __ldg(g_rowptr + w + 1);
  float4 acc = *(const float4*)(g_g + (size_t)w * 128 + lane * 4);
  for (int e = beg; e < end; e++) {
    int s = __ldg(g_eidx + e);
    float4 v = __ldg((const float4*)(g_g + (size_t)s * 128 + lane * 4));
    acc.x += v.x; acc.y += v.y; acc.z += v.z; acc.w += v.w;
  }
  *(float4*)(g_agg + (size_t)w * 128 + lane * 4) = acc;
}

__global__ void k_gather_narrow(int n, int D) {  // D = 40, lanes 0..9 active
  int w    = (blockIdx.x * blockDim.x + threadIdx.x) >> 5;
  int lane = threadIdx.x & 31;
  if (w >= n) return;
  int c = lane * 4;
  if (c >= D) return;
  int beg = __ldg(g_rowptr + w);
  int end = __ldg(g_rowptr + w + 1);
  float4 acc = *(const float4*)(g_g + (size_t)w * D + c);
  for (int e = beg; e < end; e++) {
    int s = __ldg(g_eidx + e);
    float4 v = __ldg((const float4*)(g_g + (size_t)s * D + c));
    acc.x += v.x; acc.y += v.y; acc.z += v.z; acc.w += v.w;
  }
  *(float4*)(g_agg + (size_t)w * D + c) = acc;
}

// ---------------- final output: out = agg * dinv + b ----------------

__global__ void k_finalize(const float* __restrict__ bias, float* __restrict__ out,
                           int M, int D) {
  int per_row = D >> 2;
  int t = blockIdx.x * blockDim.x + threadIdx.x;
  if (t >= M * per_row) return;
  int row = t / per_row;
  int c4  = t - row * per_row;
  size_t off = (size_t)row * D + (size_t)c4 * 4;
  float s = g_dinv[row];
  float4 v = *(const float4*)(g_agg + off);
  float4 b = *(const float4*)(bias + c4 * 4);
  v.x = v.x * s + b.x;
  v.y = v.y * s + b.y;
  v.z = v.z * s + b.z;
  v.w = v.w * s + b.w;
  *(float4*)(out + off) = v;
}

// ---------------- host launcher ----------------

extern "C" void kernel_launch(void* const* d_in, const int* in_sizes, int n_in,
                              void* d_out, int out_size) {
  const float* x  = (const float*)d_in[0];
  const int*   ei = (const int*)d_in[1];
  const float* W[4] = {(const float*)d_in[2], (const float*)d_in[4],
                       (const float*)d_in[6], (const float*)d_in[8]};
  const float* b[4] = {(const float*)d_in[3], (const float*)d_in[5],
                       (const float*)d_in[7], (const float*)d_in[9]};

  int M = in_sizes[0] / FD;  // 100000
  int E = in_sizes[1] / 2;   // 500000
  const int* src = ei;
  const int* dst = ei + E;

  float* agg;
  cudaGetSymbolAddress((void**)&agg, g_agg);

  // degree + CSR build
  int nscan = (M + SCAN_B - 1) / SCAN_B;  // 196
  k_zero_cnt<<<(M + 255) / 256, 256>>>(M);
  k_count<<<(E + 255) / 256, 256>>>(dst, E);
  k_deg_rsqrt<<<(M + 255) / 256, 256>>>(M);
  k_scan1<<<nscan, SCAN_B>>>(M);
  k_scan2<<<1, 256>>>(nscan);
  k_scan3<<<nscan, SCAN_B>>>(M);
  k_fill_init<<<(M + 255) / 256, 256>>>(M);
  k_fill<<<(E + 255) / 256, 256>>>(src, dst, E);

  int GB = (M + 127) / 128;            // 782
  int gatherB = (M * 32 + 255) / 256;  // 12500

  // layer 0 (A = x raw)
  k_gemm_wide<false><<<GB, 256>>>(x, W[0], b[0], M);
  k_gather<<<gatherB, 256>>>(M);
  // layers 1-2 (finalize of previous layer fused into A load)
  k_gemm_wide<true><<<GB, 256>>>(agg, W[1], b[0], M);
  k_gather<<<gatherB, 256>>>(M);
  k_gemm_wide<true><<<GB, 256>>>(agg, W[2], b[1], M);
  k_gather<<<gatherB, 256>>>(M);
  // layer 3: D = 40
  k_gemm_narrow<<<GB, 256>>>(agg, W[3], b[2], M, 40);
  k_gather_narrow<<<gatherB, 256>>>(M, 40);
  k_finalize<<<(M * 10 + 255) / 256, 256>>>(b[3], (float*)d_out, M, 40);
}

// round 9
// speedup vs baseline: 1.2332x; 1.0195x over previous
#include <cuda_runtime.h>
#include <cstdint>

// GCN, 4 layers: h' = relu( D^-1/2 (A+I) D^-1/2 (h W) + b )
// g = (h@W)*dinv[row]  (GEMM, FFMA2 with A pre-duplicated in smem)
// agg[d] = g[d] + sum_{(s->d)} g[s]   (CSR gather, one write per node)
// relu(agg*dinv + b) of layer l fused into layer l+1's A-tile load.
// Last layer: gather + finalize fused, writes d_out directly.

#define NN 100000
#define EE 500000
#define FD 128

__device__ float g_dinv[NN];
__device__ float g_g[(size_t)NN * FD];
__device__ float g_agg[(size_t)NN * FD];
// CSR (dst-major)
__device__ int g_cnt[NN];
__device__ int g_rowptr[NN + 1];
__device__ int g_fill[NN];
__device__ int g_eidx[EE];
__device__ int g_bsums[256];

// ---------------- degree + CSR build ----------------

__global__ void k_zero_cnt(int n) {
  int i = blockIdx.x * blockDim.x + threadIdx.x;
  if (i < n) g_cnt[i] = 0;
}
__global__ void k_count(const int* __restrict__ dst, int e) {
  int i = blockIdx.x * blockDim.x + threadIdx.x;
  if (i < e) atomicAdd(&g_cnt[dst[i]], 1);
}
__global__ void k_deg_rsqrt(int n) {
  int i = blockIdx.x * blockDim.x + threadIdx.x;
  if (i < n) g_dinv[i] = rsqrtf((float)(1 + g_cnt[i]));  // +1 self loop
}

#define SCAN_B 512
__global__ void k_scan1(int n) {  // block-local inclusive scan -> rowptr[i+1]
  __shared__ int sm[SCAN_B];
  int i = blockIdx.x * SCAN_B + threadIdx.x;
  sm[threadIdx.x] = (i < n) ? g_cnt[i] : 0;
  __syncthreads();
  for (int off = 1; off < SCAN_B; off <<= 1) {
    int t = (threadIdx.x >= off) ? sm[threadIdx.x - off] : 0;
    __syncthreads();
    sm[threadIdx.x] += t;
    __syncthreads();
  }
  if (i < n) g_rowptr[i + 1] = sm[threadIdx.x];
  if (threadIdx.x == SCAN_B - 1) g_bsums[blockIdx.x] = sm[threadIdx.x];
  if (i == 0) g_rowptr[0] = 0;
}
__global__ void k_scan2(int nb) {  // single-block scan of block sums
  __shared__ int sm[256];
  sm[threadIdx.x] = (threadIdx.x < nb) ? g_bsums[threadIdx.x] : 0;
  __syncthreads();
  for (int off = 1; off < 256; off <<= 1) {
    int t = (threadIdx.x >= off) ? sm[threadIdx.x - off] : 0;
    __syncthreads();
    sm[threadIdx.x] += t;
    __syncthreads();
  }
  if (threadIdx.x < nb) g_bsums[threadIdx.x] = sm[threadIdx.x];
}
__global__ void k_scan3(int n) {  // add carried offsets; also init g_fill
  int i = blockIdx.x * SCAN_B + threadIdx.x;
  if (i < n) {
    int v = g_rowptr[i + 1];
    if (blockIdx.x > 0) v += g_bsums[blockIdx.x - 1];
    g_rowptr[i + 1] = v;
    if (i + 1 < n) g_fill[i + 1] = v;   // fill[i] = rowptr[i]
    if (i == 0) g_fill[0] = 0;
  }
}
__global__ void k_fill(const int* __restrict__ src, const int* __restrict__ dst,
                       int e) {
  int i = blockIdx.x * blockDim.x + threadIdx.x;
  if (i < e) {
    int p = atomicAdd(&g_fill[dst[i]], 1);
    g_eidx[p] = src[i];
  }
}

// ---------------- wide GEMM (128x128 tile, 256 thr, 8x8 f32x2/thread) --------
// A duplicated in smem: As2[k][row] = (a, a) so FFMA2 consumes LDS directly.
// FUSE: A' = relu(A*dinv[row] + bias[k]) applied on load.

template <bool FUSE>
__global__ __launch_bounds__(256, 2)
void k_gemm_wide(const float* __restrict__ A, const float* __restrict__ B,
                 const float* __restrict__ bias, int M) {
  __shared__ float2 As2[2][8][128];
  __shared__ float  Bs[2][8][128];

  const int tid = threadIdx.x;
  const int bm  = blockIdx.x * 128;
  const int tx  = tid & 15;
  const int ty  = tid >> 4;

  const int aRow = tid >> 1;
  const int aCol = (tid & 1) * 4;
  const int arow = bm + aRow;
  const bool aIn = arow < M;
  const float sA = aIn ? g_dinv[arow] : 0.0f;
  const float* Aptr = A + (size_t)arow * 128 + aCol;

  const int bRow = tid >> 5;
  const int bCol = (tid & 31) * 4;

  unsigned long long acc[8][4];
#pragma unroll
  for (int i = 0; i < 8; i++)
#pragma unroll
    for (int j = 0; j < 4; j++) acc[i][j] = 0ull;

  const float4 zero4 = make_float4(0.f, 0.f, 0.f, 0.f);

#define LOAD_A(k0, av)                                              \
  do {                                                              \
    av = aIn ? *(const float4*)(Aptr + (k0)) : zero4;               \
    if (FUSE && aIn) {                                              \
      float4 c = *(const float4*)(bias + (k0) + aCol);              \
      av.x = fmaxf(av.x * sA + c.x, 0.f);                           \
      av.y = fmaxf(av.y * sA + c.y, 0.f);                           \
      av.z = fmaxf(av.z * sA + c.z, 0.f);                           \
      av.w = fmaxf(av.w * sA + c.w, 0.f);                           \
    }                                                               \
  } while (0)

#define STORE_TILES(bi, av, bv)                                     \
  do {                                                              \
    As2[bi][aCol + 0][aRow] = make_float2(av.x, av.x);              \
    As2[bi][aCol + 1][aRow] = make_float2(av.y, av.y);              \
    As2[bi][aCol + 2][aRow] = make_float2(av.z, av.z);              \
    As2[bi][aCol + 3][aRow] = make_float2(av.w, av.w);              \
    *(float4*)&Bs[bi][bRow][bCol] = bv;                             \
  } while (0)

  {
    float4 av, bv;
    LOAD_A(0, av);
    bv = *(const float4*)(B + (size_t)bRow * 128 + bCol);
    STORE_TILES(0, av, bv);
  }
  __syncthreads();

  int buf = 0;
  for (int k0 = 8; k0 <= 128; k0 += 8) {
    float4 av, bv;
    if (k0 < 128) {
      LOAD_A(k0, av);
      bv = *(const float4*)(B + (size_t)(k0 + bRow) * 128 + bCol);
    }
#pragma unroll
    for (int kk = 0; kk < 8; kk++) {
      unsigned long long a2[8];
      *(ulonglong2*)(a2)     = *(const ulonglong2*)&As2[buf][kk][ty * 8];
      *(ulonglong2*)(a2 + 2) = *(const ulonglong2*)&As2[buf][kk][ty * 8 + 2];
      *(ulonglong2*)(a2 + 4) = *(const ulonglong2*)&As2[buf][kk][ty * 8 + 4];
      *(ulonglong2*)(a2 + 6) = *(const ulonglong2*)&As2[buf][kk][ty * 8 + 6];
      unsigned long long bb[4];
      *(ulonglong2*)(bb)     = *(const ulonglong2*)&Bs[buf][kk][tx * 8];
      *(ulonglong2*)(bb + 2) = *(const ulonglong2*)&Bs[buf][kk][tx * 8 + 4];
#pragma unroll
      for (int i = 0; i < 8; i++)
#pragma unroll
        for (int j = 0; j < 4; j++)
          asm("fma.rn.f32x2 %0, %1, %2, %0;"
              : "+l"(acc[i][j]) : "l"(a2[i]), "l"(bb[j]));
    }
    if (k0 < 128) {
      STORE_TILES(buf ^ 1, av, bv);
      __syncthreads();
      buf ^= 1;
    }
  }
#undef LOAD_A
#undef STORE_TILES

#pragma unroll
  for (int i = 0; i < 8; i++) {
    int r = bm + ty * 8 + i;
    if (r >= M) continue;
    float s = g_dinv[r];
    float* out = g_g + (size_t)r * 128 + tx * 8;
#pragma unroll
    for (int j = 0; j < 4; j += 2) {
      float x0, x1, x2, x3;
      asm("mov.b64 {%0, %1}, %2;" : "=f"(x0), "=f"(x1) : "l"(acc[i][j]));
      asm("mov.b64 {%0, %1}, %2;" : "=f"(x2), "=f"(x3) : "l"(acc[i][j + 1]));
      *(float4*)(out + j * 2) = make_float4(x0 * s, x1 * s, x2 * s, x3 * s);
    }
  }
}

// ---------------- narrow GEMM (D=40, TN=64, FFMA2) ----------------

__global__ __launch_bounds__(256, 2)
void k_gemm_narrow(const float* __restrict__ A, const float* __restrict__ B,
                   const float* __restrict__ bias, int M, int D) {
  constexpr int TN = 64;
  __shared__ float As[2][8][128];
  __shared__ float Bs[2][8][TN];

  const int tid = threadIdx.x;
  const int bm  = blockIdx.x * 128;
  const int tx  = tid & 15;
  const int ty  = tid >> 4;

  const int aRow = tid >> 1;
  const int aCol = (tid & 1) * 4;
  const int arow = bm + aRow;
  const bool aIn = arow < M;
  const float sA = aIn ? g_dinv[arow] : 0.0f;
  const float* Aptr = A + (size_t)arow * 128 + aCol;

  const int bRow = tid / (TN / 4);
  const int bCol = (tid % (TN / 4)) * 4;
  const bool bThread = tid < 2 * TN;
  const bool bIn = bThread && (bCol < D);

  unsigned long long acc[8][2];
#pragma unroll
  for (int i = 0; i < 8; i++) { acc[i][0] = 0ull; acc[i][1] = 0ull; }

  const float4 zero4 = make_float4(0.f, 0.f, 0.f, 0.f);

#define NLOAD_A(k0, av)                                             \
  do {                                                              \
    av = aIn ? *(const float4*)(Aptr + (k0)) : zero4;               \
    float4 c = aIn ? *(const float4*)(bias + (k0) + aCol) : zero4;  \
    av.x = fmaxf(av.x * sA + c.x, 0.f);                             \
    av.y = fmaxf(av.y * sA + c.y, 0.f);                             \
    av.z = fmaxf(av.z * sA + c.z, 0.f);                             \
    av.w = fmaxf(av.w * sA + c.w, 0.f);                             \
  } while (0)

#define NSTORE(bi, av, bv)                                          \
  do {                                                              \
    As[bi][aCol + 0][aRow] = av.x;                                  \
    As[bi][aCol + 1][aRow] = av.y;                                  \
    As[bi][aCol + 2][aRow] = av.z;                                  \
    As[bi][aCol + 3][aRow] = av.w;                                  \
    if (bThread) *(float4*)&Bs[bi][bRow][bCol] = bv;                \
  } while (0)

  {
    float4 av, bv;
    NLOAD_A(0, av);
    bv = bIn ? *(const float4*)(B + (size_t)bRow * D + bCol) : zero4;
    NSTORE(0, av, bv);
  }
  __syncthreads();

  int buf = 0;
  for (int k0 = 8; k0 <= 128; k0 += 8) {
    float4 av, bv;
    if (k0 < 128) {
      NLOAD_A(k0, av);
      bv = bIn ? *(const float4*)(B + (size_t)(k0 + bRow) * D + bCol) : zero4;
    }
#pragma unroll
    for (int kk = 0; kk < 8; kk++) {
      float a[8];
      *(float4*)(a)     = *(const float4*)&As[buf][kk][ty * 8];
      *(float4*)(a + 4) = *(const float4*)&As[buf][kk][ty * 8 + 4];
      ulonglong2 bb = *(const ulonglong2*)&Bs[buf][kk][tx * 4];
#pragma unroll
      for (int i = 0; i < 8; i++) {
        unsigned long long a2;
        asm("mov.b64 %0, {%1, %1};" : "=l"(a2) : "f"(a[i]));
        asm("fma.rn.f32x2 %0, %1, %2, %0;" : "+l"(acc[i][0]) : "l"(a2), "l"(bb.x));
        asm("fma.rn.f32x2 %0, %1, %2, %0;" : "+l"(acc[i][1]) : "l"(a2), "l"(bb.y));
      }
    }
    if (k0 < 128) {
      NSTORE(buf ^ 1, av, bv);
      __syncthreads();
      buf ^= 1;
    }
  }
#undef NLOAD_A
#undef NSTORE

#pragma unroll
  for (int i = 0; i < 8; i++) {
    int r = bm + ty * 8 + i;
    if (r >= M) continue;
    int col = tx * 4;
    if (col >= D) continue;
    float s = g_dinv[r];
    float x0, x1, x2, x3;
    asm("mov.b64 {%0, %1}, %2;" : "=f"(x0), "=f"(x1) : "l"(acc[i][0]));
    asm("mov.b64 {%0, %1}, %2;" : "=f"(x2), "=f"(x3) : "l"(acc[i][1]));
    *(float4*)(g_g + (size_t)r * D + col) =
        make_float4(x0 * s, x1 * s, x2 * s, x3 * s);
  }
}

// ---------------- CSR gather: agg[d] = g[d] + sum g[src] ----------------

__global__ void k_gather(int n) {  // D = 128, warp per node
  int w    = (blockIdx.x * blockDim.x + threadIdx.x) >> 5;
  int lane = threadIdx.x & 31;
  if (w >= n) return;
  int beg = __ldg(g_rowptr + w);
  int end = __ldg(g_rowptr + w + 1);
  float4 acc = *(const float4*)(g_g + (size_t)w * 128 + lane * 4);
  for (int e = beg; e < end; e++) {
    int s = __ldg(g_eidx + e);
    float4 v = __ldg((const float4*)(g_g + (size_t)s * 128 + lane * 4));
    acc.x += v.x; acc.y += v.y; acc.z += v.z; acc.w += v.w;
  }
  *(float4*)(g_agg + (size_t)w * 128 + lane * 4) = acc;
}

// last layer (D=40): gather + finalize fused, half-warp per node, write d_out.
__global__ void k_gather_out(const float* __restrict__ bias,
                             float* __restrict__ out, int n, int D) {
  int t    = blockIdx.x * blockDim.x + threadIdx.x;
  int half = t >> 4;             // half-warp index
  int lane = t & 15;             // lane within half-warp
  if (half >= n) return;
  int node = half;
  int c = lane * 4;
  if (c >= D) return;
  int beg = __ldg(g_rowptr + node);
  int end = __ldg(g_rowptr + node + 1);
  float4 acc = *(const float4*)(g_g + (size_t)node * D + c);
  for (int e = beg; e < end; e++) {
    int s = __ldg(g_eidx + e);
    float4 v = __ldg((const float4*)(g_g + (size_t)s * D + c));
    acc.x += v.x; acc.y += v.y; acc.z += v.z; acc.w += v.w;
  }
  float sc = g_dinv[node];
  float4 b = *(const float4*)(bias + c);
  acc.x = acc.x * sc + b.x;
  acc.y = acc.y * sc + b.y;
  acc.z = acc.z * sc + b.z;
  acc.w = acc.w * sc + b.w;
  *(float4*)(out + (size_t)node * D + c) = acc;
}

// ---------------- host launcher ----------------

extern "C" void kernel_launch(void* const* d_in, const int* in_sizes, int n_in,
                              void* d_out, int out_size) {
  const float* x  = (const float*)d_in[0];
  const int*   ei = (const int*)d_in[1];
  const float* W[4] = {(const float*)d_in[2], (const float*)d_in[4],
                       (const float*)d_in[6], (const float*)d_in[8]};
  const float* b[4] = {(const float*)d_in[3], (const float*)d_in[5],
                       (const float*)d_in[7], (const float*)d_in[9]};

  int M = in_sizes[0] / FD;  // 100000
  int E = in_sizes[1] / 2;   // 500000
  const int* src = ei;
  const int* dst = ei + E;

  float* agg;
  cudaGetSymbolAddress((void**)&agg, g_agg);

  int nscan = (M + SCAN_B - 1) / SCAN_B;  // 196
  int GB = (M + 127) / 128;               // 782
  int gatherB = (M * 32 + 255) / 256;     // 12500

  // degree (launches 1-3)
  k_zero_cnt<<<(M + 255) / 256, 256>>>(M);
  k_count<<<(E + 255) / 256, 256>>>(dst, E);
  k_deg_rsqrt<<<(M + 255) / 256, 256>>>(M);
  // scan prefix (4-5)
  k_scan1<<<nscan, SCAN_B>>>(M);
  k_scan2<<<1, 256>>>(nscan);
  // layer-0 GEMM as 6th launch (only needs dinv) -> ncu -s 5 -c 1 profiles it
  k_gemm_wide<false><<<GB, 256>>>(x, W[0], b[0], M);
  // finish CSR (7-8)
  k_scan3<<<nscan, SCAN_B>>>(M);
  k_fill<<<(E + 255) / 256, 256>>>(src, dst, E);

  // layer 0 aggregate
  k_gather<<<gatherB, 256>>>(M);
  // layers 1-2 (finalize of previous layer fused into A load)
  k_gemm_wide<true><<<GB, 256>>>(agg, W[1], b[0], M);
  k_gather<<<gatherB, 256>>>(M);
  k_gemm_wide<true><<<GB, 256>>>(agg, W[2], b[1], M);
  k_gather<<<gatherB, 256>>>(M);
  // layer 3: D = 40; gather+finalize fused -> d_out
  k_gemm_narrow<<<GB, 256>>>(agg, W[3], b[2], M, 40);
  k_gather_out<<<(M * 16 + 255) / 256, 256>>>(b[3], (float*)d_out, M, 40);
}

// round 10
// speedup vs baseline: 1.6084x; 1.3042x over previous
#include <cuda_runtime.h>
#include <cuda_bf16.h>
#include <cstdint>

// GCN, 4 layers: h' = relu( D^-1/2 (A+I) D^-1/2 (h W) + b )
// Wide GEMMs (128->128) on tensor cores via legacy mma.sync bf16 (bf16x3
// split: D = AhBh + AhBl + AlBh, fp32 accum; ~1e-5 rel err).
// Fragments are PRE-ARRANGED in smem by the fp32->bf16 convert loops, so the
// MMA inner loop is pure conflict-free LDS + HMMA (no ldmatrix, no swizzle).
// agg[d] = g[d] + sum_{(s->d)} g[s] via CSR gather; relu(agg*dinv+b) of layer
// l fused into layer l+1's A load. Narrow layer (->40) stays SIMT FFMA2.

#define NN 100000
#define EE 500000
#define FD 128

__device__ float g_dinv[NN];
__device__ float g_g[(size_t)NN * FD];
__device__ float g_agg[(size_t)NN * FD];
// CSR (dst-major)
__device__ int g_cnt[NN];
__device__ int g_rowptr[NN + 1];
__device__ int g_fill[NN];
__device__ int g_eidx[EE];
__device__ int g_bsums[256];

// ---------------- degree + CSR build ----------------

__global__ void k_zero_cnt(int n) {
  int i = blockIdx.x * blockDim.x + threadIdx.x;
  if (i < n) g_cnt[i] = 0;
}
__global__ void k_count(const int* __restrict__ dst, int e) {
  int i = blockIdx.x * blockDim.x + threadIdx.x;
  if (i < e) atomicAdd(&g_cnt[dst[i]], 1);
}
__global__ void k_deg_rsqrt(int n) {
  int i = blockIdx.x * blockDim.x + threadIdx.x;
  if (i < n) g_dinv[i] = rsqrtf((float)(1 + g_cnt[i]));  // +1 self loop
}

#define SCAN_B 512
__global__ void k_scan1(int n) {
  __shared__ int sm[SCAN_B];
  int i = blockIdx.x * SCAN_B + threadIdx.x;
  sm[threadIdx.x] = (i < n) ? g_cnt[i] : 0;
  __syncthreads();
  for (int off = 1; off < SCAN_B; off <<= 1) {
    int t = (threadIdx.x >= off) ? sm[threadIdx.x - off] : 0;
    __syncthreads();
    sm[threadIdx.x] += t;
    __syncthreads();
  }
  if (i < n) g_rowptr[i + 1] = sm[threadIdx.x];
  if (threadIdx.x == SCAN_B - 1) g_bsums[blockIdx.x] = sm[threadIdx.x];
  if (i == 0) g_rowptr[0] = 0;
}
__global__ void k_scan2(int nb) {
  __shared__ int sm[256];
  sm[threadIdx.x] = (threadIdx.x < nb) ? g_bsums[threadIdx.x] : 0;
  __syncthreads();
  for (int off = 1; off < 256; off <<= 1) {
    int t = (threadIdx.x >= off) ? sm[threadIdx.x - off] : 0;
    __syncthreads();
    sm[threadIdx.x] += t;
    __syncthreads();
  }
  if (threadIdx.x < nb) g_bsums[threadIdx.x] = sm[threadIdx.x];
}
__global__ void k_scan3(int n) {  // add carried offsets; also init g_fill
  int i = blockIdx.x * SCAN_B + threadIdx.x;
  if (i < n) {
    int v = g_rowptr[i + 1];
    if (blockIdx.x > 0) v += g_bsums[blockIdx.x - 1];
    g_rowptr[i + 1] = v;
    if (i + 1 < n) g_fill[i + 1] = v;
    if (i == 0) g_fill[0] = 0;
  }
}
__global__ void k_fill(const int* __restrict__ src, const int* __restrict__ dst,
                       int e) {
  int i = blockIdx.x * blockDim.x + threadIdx.x;
  if (i < e) {
    int p = atomicAdd(&g_fill[dst[i]], 1);
    g_eidx[p] = src[i];
  }
}

// ---------------- wide GEMM via mma.sync bf16x3 ----------------
// Fragment arrays (u32):
//   A: [mtile 8][ktile 8][lane 32][j 4]   (m16k16 row-major A fragment)
//   B: [ktile 8][ntile 16][lane 32][j 2]  (k16n8 col-major B fragment)
#define A_FRAG(mt, kt, lane, j) ((((mt) * 8 + (kt)) * 32 + (lane)) * 4 + (j))
#define B_FRAG(kt, nt, lane, j) ((((kt) * 16 + (nt)) * 32 + (lane)) * 2 + (j))

__device__ __forceinline__ uint32_t pack_bf16(float x, float y) {
  __nv_bfloat162 p = __floats2bfloat162_rn(x, y);  // x -> low half
  return *(uint32_t*)&p;
}

__device__ __forceinline__ void mma_bf16(float* c, const uint32_t* a,
                                         const uint32_t* b) {
  asm volatile(
      "mma.sync.aligned.m16n8k16.row.col.f32.bf16.bf16.f32 "
      "{%0,%1,%2,%3}, {%4,%5,%6,%7}, {%8,%9}, {%0,%1,%2,%3};"
      : "+f"(c[0]), "+f"(c[1]), "+f"(c[2]), "+f"(c[3])
      : "r"(a[0]), "r"(a[1]), "r"(a[2]), "r"(a[3]), "r"(b[0]), "r"(b[1]));
}

template <bool FUSE>
__global__ __launch_bounds__(256, 1)
void k_gemm_mma(const float* __restrict__ A, const float* __restrict__ W,
                const float* __restrict__ bias, int M) {
  extern __shared__ uint32_t sm[];
  uint32_t* sAh = sm;            // 8192 u32
  uint32_t* sAl = sm + 8192;
  uint32_t* sBh = sm + 16384;
  uint32_t* sBl = sm + 24576;

  const int tid = threadIdx.x;
  const int wid = tid >> 5;
  const int lane = tid & 31;
  const int bm = blockIdx.x * 128;

  // ---- B: load fp32 [k][n], split hi/lo, write fragment slots ----
#pragma unroll
  for (int it = 0; it < 32; it++) {
    int idx = it * 256 + tid;       // 0..8191 frag-pairs
    int n = idx & 127;
    int kp = idx >> 7;              // k pair index 0..63, k = 2*kp
    float v0 = W[(size_t)(2 * kp) * 128 + n];
    float v1 = W[(size_t)(2 * kp + 1) * 128 + n];
    __nv_bfloat16 h0 = __float2bfloat16(v0), h1 = __float2bfloat16(v1);
    float l0 = v0 - __bfloat162float(h0), l1 = v1 - __bfloat162float(h1);
    int kt = kp >> 3;
    int bl = (n & 7) * 4 + (kp & 3);
    int j = (kp >> 2) & 1;
    int slot = B_FRAG(kt, n >> 3, bl, j);
    sBh[slot] = pack_bf16(__bfloat162float(h0), __bfloat162float(h1));
    sBl[slot] = pack_bf16(l0, l1);
  }

  // ---- A: load fp32 [m][k] (FUSE: relu(a*dinv+bias)), split, write frags ----
#pragma unroll
  for (int it = 0; it < 32; it++) {
    int idx = it * 256 + tid;
    int m = idx >> 6;
    int kp = idx & 63;              // k = 2*kp
    int arow = bm + m;
    float2 v = make_float2(0.f, 0.f);
    if (arow < M) {
      v = *(const float2*)(A + (size_t)arow * 128 + 2 * kp);
      if (FUSE) {
        float s = g_dinv[arow];
        float2 c = *(const float2*)(bias + 2 * kp);
        v.x = fmaxf(v.x * s + c.x, 0.f);
        v.y = fmaxf(v.y * s + c.y, 0.f);
      }
    }
    __nv_bfloat16 h0 = __float2bfloat16(v.x), h1 = __float2bfloat16(v.y);
    float l0 = v.x - __bfloat162float(h0), l1 = v.y - __bfloat162float(h1);
    int r = m & 15, mt = m >> 4, kt = kp >> 3;
    int al = (r & 7) * 4 + (kp & 3);
    int j = (r >> 3) + ((kp >> 2) & 1) * 2;
    int slot = A_FRAG(mt, kt, al, j);
    sAh[slot] = pack_bf16(__bfloat162float(h0), __bfloat162float(h1));
    sAl[slot] = pack_bf16(l0, l1);
  }
  __syncthreads();

  // ---- MMA mainloop: warp tile 32(m) x 64(n); 4 m-warps x 2 n-warps ----
  const int mw = wid & 3;   // m-warp: mtiles mw*2, mw*2+1
  const int nw = wid >> 2;  // n-warp: ntiles nw*8 .. nw*8+7

  float c[2][8][4];
#pragma unroll
  for (int mi = 0; mi < 2; mi++)
#pragma unroll
    for (int nt = 0; nt < 8; nt++)
#pragma unroll
      for (int q = 0; q < 4; q++) c[mi][nt][q] = 0.f;

#pragma unroll
  for (int kt = 0; kt < 8; kt++) {
    uint32_t ah[2][4], al_[2][4];
#pragma unroll
    for (int mi = 0; mi < 2; mi++) {
      *(uint4*)ah[mi]  = *(const uint4*)&sAh[A_FRAG(mw * 2 + mi, kt, lane, 0)];
      *(uint4*)al_[mi] = *(const uint4*)&sAl[A_FRAG(mw * 2 + mi, kt, lane, 0)];
    }
#pragma unroll
    for (int nh = 0; nh < 2; nh++) {
      uint32_t bh[4][2], bl_[4][2];
#pragma unroll
      for (int nt = 0; nt < 4; nt++) {
        int ntile = nw * 8 + nh * 4 + nt;
        *(uint2*)bh[nt]  = *(const uint2*)&sBh[B_FRAG(kt, ntile, lane, 0)];
        *(uint2*)bl_[nt] = *(const uint2*)&sBl[B_FRAG(kt, ntile, lane, 0)];
      }
#pragma unroll
      for (int mi = 0; mi < 2; mi++)
#pragma unroll
        for (int nt = 0; nt < 4; nt++) {
          float* cc = c[mi][nh * 4 + nt];
          mma_bf16(cc, ah[mi], bh[nt]);   // Ah*Bh
          mma_bf16(cc, ah[mi], bl_[nt]);  // Ah*Bl
          mma_bf16(cc, al_[mi], bh[nt]);  // Al*Bh
        }
    }
  }

  // ---- epilogue: g = acc * dinv[row] ----
#pragma unroll
  for (int mi = 0; mi < 2; mi++) {
    int r0 = bm + mw * 32 + mi * 16 + (lane >> 2);
    int r1 = r0 + 8;
    float s0 = (r0 < M) ? g_dinv[r0] : 0.f;
    float s1 = (r1 < M) ? g_dinv[r1] : 0.f;
#pragma unroll
    for (int nt = 0; nt < 8; nt++) {
      int col = nw * 64 + nt * 8 + (lane & 3) * 2;
      if (r0 < M)
        *(float2*)(g_g + (size_t)r0 * 128 + col) =
            make_float2(c[mi][nt][0] * s0, c[mi][nt][1] * s0);
      if (r1 < M)
        *(float2*)(g_g + (size_t)r1 * 128 + col) =
            make_float2(c[mi][nt][2] * s1, c[mi][nt][3] * s1);
    }
  }
}

// ---------------- narrow GEMM (D=40, TN=64, FFMA2) ----------------

__global__ __launch_bounds__(256, 2)
void k_gemm_narrow(const float* __restrict__ A, const float* __restrict__ B,
                   const float* __restrict__ bias, int M, int D) {
  constexpr int TN = 64;
  __shared__ float As[2][8][128];
  __shared__ float Bs[2][8][TN];

  const int tid = threadIdx.x;
  const int bm  = blockIdx.x * 128;
  const int tx  = tid & 15;
  const int ty  = tid >> 4;

  const int aRow = tid >> 1;
  const int aCol = (tid & 1) * 4;
  const int arow = bm + aRow;
  const bool aIn = arow < M;
  const float sA = aIn ? g_dinv[arow] : 0.0f;
  const float* Aptr = A + (size_t)arow * 128 + aCol;

  const int bRow = tid / (TN / 4);
  const int bCol = (tid % (TN / 4)) * 4;
  const bool bThread = tid < 2 * TN;
  const bool bIn = bThread && (bCol < D);

  unsigned long long acc[8][2];
#pragma unroll
  for (int i = 0; i < 8; i++) { acc[i][0] = 0ull; acc[i][1] = 0ull; }

  const float4 zero4 = make_float4(0.f, 0.f, 0.f, 0.f);

#define NLOAD_A(k0, av)                                             \
  do {                                                              \
    av = aIn ? *(const float4*)(Aptr + (k0)) : zero4;               \
    float4 c = aIn ? *(const float4*)(bias + (k0) + aCol) : zero4;  \
    av.x = fmaxf(av.x * sA + c.x, 0.f);                             \
    av.y = fmaxf(av.y * sA + c.y, 0.f);                             \
    av.z = fmaxf(av.z * sA + c.z, 0.f);                             \
    av.w = fmaxf(av.w * sA + c.w, 0.f);                             \
  } while (0)

#define NSTORE(bi, av, bv)                                          \
  do {                                                              \
    As[bi][aCol + 0][aRow] = av.x;                                  \
    As[bi][aCol + 1][aRow] = av.y;                                  \
    As[bi][aCol + 2][aRow] = av.z;                                  \
    As[bi][aCol + 3][aRow] = av.w;                                  \
    if (bThread) *(float4*)&Bs[bi][bRow][bCol] = bv;                \
  } while (0)

  {
    float4 av, bv;
    NLOAD_A(0, av);
    bv = bIn ? *(const float4*)(B + (size_t)bRow * D + bCol) : zero4;
    NSTORE(0, av, bv);
  }
  __syncthreads();

  int buf = 0;
  for (int k0 = 8; k0 <= 128; k0 += 8) {
    float4 av, bv;
    if (k0 < 128) {
      NLOAD_A(k0, av);
      bv = bIn ? *(const float4*)(B + (size_t)(k0 + bRow) * D + bCol) : zero4;
    }
#pragma unroll
    for (int kk = 0; kk < 8; kk++) {
      float a[8];
      *(float4*)(a)     = *(const float4*)&As[buf][kk][ty * 8];
      *(float4*)(a + 4) = *(const float4*)&As[buf][kk][ty * 8 + 4];
      ulonglong2 bb = *(const ulonglong2*)&Bs[buf][kk][tx * 4];
#pragma unroll
      for (int i = 0; i < 8; i++) {
        unsigned long long a2;
        asm("mov.b64 %0, {%1, %1};" : "=l"(a2) : "f"(a[i]));
        asm("fma.rn.f32x2 %0, %1, %2, %0;" : "+l"(acc[i][0]) : "l"(a2), "l"(bb.x));
        asm("fma.rn.f32x2 %0, %1, %2, %0;" : "+l"(acc[i][1]) : "l"(a2), "l"(bb.y));
      }
    }
    if (k0 < 128) {
      NSTORE(buf ^ 1, av, bv);
      __syncthreads();
      buf ^= 1;
    }
  }
#undef NLOAD_A
#undef NSTORE

#pragma unroll
  for (int i = 0; i < 8; i++) {
    int r = bm + ty * 8 + i;
    if (r >= M) continue;
    int col = tx * 4;
    if (col >= D) continue;
    float s = g_dinv[r];
    float x0, x1, x2, x3;
    asm("mov.b64 {%0, %1}, %2;" : "=f"(x0), "=f"(x1) : "l"(acc[i][0]));
    asm("mov.b64 {%0, %1}, %2;" : "=f"(x2), "=f"(x3) : "l"(acc[i][1]));
    *(float4*)(g_g + (size_t)r * D + col) =
        make_float4(x0 * s, x1 * s, x2 * s, x3 * s);
  }
}

// ---------------- CSR gather: agg[d] = g[d] + sum g[src] ----------------

__global__ void k_gather(int n) {  // D = 128, warp per node
  int w    = (blockIdx.x * blockDim.x + threadIdx.x) >> 5;
  int lane = threadIdx.x & 31;
  if (w >= n) return;
  int beg = __ldg(g_rowptr + w);
  int end = __ldg(g_rowptr + w + 1);
  float4 acc = *(const float4*)(g_g + (size_t)w * 128 + lane * 4);
  for (int e = beg; e < end; e++) {
    int s = __ldg(g_eidx + e);
    float4 v = __ldg((const float4*)(g_g + (size_t)s * 128 + lane * 4));
    acc.x += v.x; acc.y += v.y; acc.z += v.z; acc.w += v.w;
  }
  *(float4*)(g_agg + (size_t)w * 128 + lane * 4) = acc;
}

// last layer (D=40): gather + finalize fused, half-warp per node, write d_out.
__global__ void k_gather_out(const float* __restrict__ bias,
                             float* __restrict__ out, int n, int D) {
  int t    = blockIdx.x * blockDim.x + threadIdx.x;
  int half = t >> 4;
  int lane = t & 15;
  if (half >= n) return;
  int node = half;
  int c = lane * 4;
  if (c >= D) return;
  int beg = __ldg(g_rowptr + node);
  int end = __ldg(g_rowptr + node + 1);
  float4 acc = *(const float4*)(g_g + (size_t)node * D + c);
  for (int e = beg; e < end; e++) {
    int s = __ldg(g_eidx + e);
    float4 v = __ldg((const float4*)(g_g + (size_t)s * D + c));
    acc.x += v.x; acc.y += v.y; acc.z += v.z; acc.w += v.w;
  }
  float sc = g_dinv[node];
  float4 b = *(const float4*)(bias + c);
  acc.x = acc.x * sc + b.x;
  acc.y = acc.y * sc + b.y;
  acc.z = acc.z * sc + b.z;
  acc.w = acc.w * sc + b.w;
  *(float4*)(out + (size_t)node * D + c) = acc;
}

// ---------------- host launcher ----------------

extern "C" void kernel_launch(void* const* d_in, const int* in_sizes, int n_in,
                              void* d_out, int out_size) {
  const float* x  = (const float*)d_in[0];
  const int*   ei = (const int*)d_in[1];
  const float* W[4] = {(const float*)d_in[2], (const float*)d_in[4],
                       (const float*)d_in[6], (const float*)d_in[8]};
  const float* b[4] = {(const float*)d_in[3], (const float*)d_in[5],
                       (const float*)d_in[7], (const float*)d_in[9]};

  int M = in_sizes[0] / FD;  // 100000
  int E = in_sizes[1] / 2;   // 500000
  const int* src = ei;
  const int* dst = ei + E;

  float* agg;
  cudaGetSymbolAddress((void**)&agg, g_agg);

  const int SMEM = 131072;  // 128 KB fragment storage
  cudaFuncSetAttribute(k_gemm_mma<false>,
                       cudaFuncAttributeMaxDynamicSharedMemorySize, SMEM);
  cudaFuncSetAttribute(k_gemm_mma<true>,
                       cudaFuncAttributeMaxDynamicSharedMemorySize, SMEM);

  int nscan = (M + SCAN_B - 1) / SCAN_B;  // 196
  int GB = (M + 127) / 128;               // 782
  int gatherB = (M * 32 + 255) / 256;     // 12500

  // degree
  k_zero_cnt<<<(M + 255) / 256, 256>>>(M);
  k_count<<<(E + 255) / 256, 256>>>(dst, E);
  k_deg_rsqrt<<<(M + 255) / 256, 256>>>(M);
  // scan prefix
  k_scan1<<<nscan, SCAN_B>>>(M);
  k_scan2<<<1, 256>>>(nscan);
  // layer-0 GEMM (needs only dinv)
  k_gemm_mma<false><<<GB, 256, SMEM>>>(x, W[0], b[0], M);
  // finish CSR
  k_scan3<<<nscan, SCAN_B>>>(M);
  k_fill<<<(E + 255) / 256, 256>>>(src, dst, E);

  // layer 0 aggregate
  k_gather<<<gatherB, 256>>>(M);
  // layers 1-2
  k_gemm_mma<true><<<GB, 256, SMEM>>>(agg, W[1], b[0], M);
  k_gather<<<gatherB, 256>>>(M);
  k_gemm_mma<true><<<GB, 256, SMEM>>>(agg, W[2], b[1], M);
  k_gather<<<gatherB, 256>>>(M);
  // layer 3: D = 40; gather+finalize fused -> d_out
  k_gemm_narrow<<<GB, 256>>>(agg, W[3], b[2], M, 40);
  k_gather_out<<<(M * 16 + 255) / 256, 256>>>(b[3], (float*)d_out, M, 40);
}

// round 11
// speedup vs baseline: 1.9636x; 1.2209x over previous
#include <cuda_runtime.h>
#include <cuda_bf16.h>
#include <cstdint>

// GCN, 4 layers: h' = relu( D^-1/2 (A+I) D^-1/2 (h W) + b )
// Wide GEMMs (128->128) on tensor cores via mma.sync bf16x3 split
// (D = AhBh + AhBl + AlBh, fp32 accum; ~5e-6 rel err).
// W fragments are pre-converted ONCE per layer into global fragment arrays
// (k_wprep); the GEMM loads them straight from L1/L2 via __ldg. Only the A
// fragments live in smem (64 KB) -> 2 CTAs/SM.
// agg[d] = g[d] + sum_{(s->d)} g[s] via CSR gather; relu(agg*dinv+b) of layer
// l fused into layer l+1's A load. Narrow layer (->40) stays SIMT FFMA2.

#define NN 100000
#define EE 500000
#define FD 128

__device__ float g_dinv[NN];
__device__ float g_g[(size_t)NN * FD];
__device__ float g_agg[(size_t)NN * FD];
// CSR (dst-major)
__device__ int g_cnt[NN];
__device__ int g_rowptr[NN + 1];
__device__ int g_fill[NN];
__device__ int g_eidx[EE];
__device__ int g_bsums[256];
// pre-converted W fragments (hi/lo), 3 wide layers x 8192 u32 each
__device__ uint32_t g_wfh[3][8192];
__device__ uint32_t g_wfl[3][8192];

// ---------------- degree + CSR build ----------------

__global__ void k_zero_cnt(int n) {
  int i = blockIdx.x * blockDim.x + threadIdx.x;
  if (i < n) g_cnt[i] = 0;
}
__global__ void k_count(const int* __restrict__ dst, int e) {
  int i = blockIdx.x * blockDim.x + threadIdx.x;
  if (i < e) atomicAdd(&g_cnt[dst[i]], 1);
}
__global__ void k_deg_rsqrt(int n) {
  int i = blockIdx.x * blockDim.x + threadIdx.x;
  if (i < n) g_dinv[i] = rsqrtf((float)(1 + g_cnt[i]));  // +1 self loop
}

#define SCAN_B 512
__global__ void k_scan1(int n) {
  __shared__ int sm[SCAN_B];
  int i = blockIdx.x * SCAN_B + threadIdx.x;
  sm[threadIdx.x] = (i < n) ? g_cnt[i] : 0;
  __syncthreads();
  for (int off = 1; off < SCAN_B; off <<= 1) {
    int t = (threadIdx.x >= off) ? sm[threadIdx.x - off] : 0;
    __syncthreads();
    sm[threadIdx.x] += t;
    __syncthreads();
  }
  if (i < n) g_rowptr[i + 1] = sm[threadIdx.x];
  if (threadIdx.x == SCAN_B - 1) g_bsums[blockIdx.x] = sm[threadIdx.x];
  if (i == 0) g_rowptr[0] = 0;
}
__global__ void k_scan2(int nb) {
  __shared__ int sm[256];
  sm[threadIdx.x] = (threadIdx.x < nb) ? g_bsums[threadIdx.x] : 0;
  __syncthreads();
  for (int off = 1; off < 256; off <<= 1) {
    int t = (threadIdx.x >= off) ? sm[threadIdx.x - off] : 0;
    __syncthreads();
    sm[threadIdx.x] += t;
    __syncthreads();
  }
  if (threadIdx.x < nb) g_bsums[threadIdx.x] = sm[threadIdx.x];
}
__global__ void k_scan3(int n) {  // add carried offsets; also init g_fill
  int i = blockIdx.x * SCAN_B + threadIdx.x;
  if (i < n) {
    int v = g_rowptr[i + 1];
    if (blockIdx.x > 0) v += g_bsums[blockIdx.x - 1];
    g_rowptr[i + 1] = v;
    if (i + 1 < n) g_fill[i + 1] = v;
    if (i == 0) g_fill[0] = 0;
  }
}
__global__ void k_fill(const int* __restrict__ src, const int* __restrict__ dst,
                       int e) {
  int i = blockIdx.x * blockDim.x + threadIdx.x;
  if (i < e) {
    int p = atomicAdd(&g_fill[dst[i]], 1);
    g_eidx[p] = src[i];
  }
}

// ---------------- fragment layout ----------------
//   A: [mtile 8][ktile 8][lane 32][j 4]   (m16k16 row-major A fragment)
//   B: [ktile 8][ntile 16][lane 32][j 2]  (k16n8 col-major B fragment)
#define A_FRAG(mt, kt, lane, j) ((((mt) * 8 + (kt)) * 32 + (lane)) * 4 + (j))
#define B_FRAG(kt, nt, lane, j) ((((kt) * 16 + (nt)) * 32 + (lane)) * 2 + (j))

__device__ __forceinline__ uint32_t pack_bf16(float x, float y) {
  __nv_bfloat162 p = __floats2bfloat162_rn(x, y);  // x -> low half
  return *(uint32_t*)&p;
}

__device__ __forceinline__ void mma_bf16(float* c, const uint32_t* a,
                                         const uint32_t* b) {
  asm volatile(
      "mma.sync.aligned.m16n8k16.row.col.f32.bf16.bf16.f32 "
      "{%0,%1,%2,%3}, {%4,%5,%6,%7}, {%8,%9}, {%0,%1,%2,%3};"
      : "+f"(c[0]), "+f"(c[1]), "+f"(c[2]), "+f"(c[3])
      : "r"(a[0]), "r"(a[1]), "r"(a[2]), "r"(a[3]), "r"(b[0]), "r"(b[1]));
}

// per-layer W -> fragment conversion (runs once, 8192 threads)
__global__ void k_wprep(const float* __restrict__ W, uint32_t* __restrict__ fh,
                        uint32_t* __restrict__ fl) {
  int idx = blockIdx.x * blockDim.x + threadIdx.x;
  if (idx >= 8192) return;
  int n = idx & 127;
  int kp = idx >> 7;  // k pair index 0..63
  float v0 = W[(size_t)(2 * kp) * 128 + n];
  float v1 = W[(size_t)(2 * kp + 1) * 128 + n];
  __nv_bfloat16 h0 = __float2bfloat16(v0), h1 = __float2bfloat16(v1);
  float l0 = v0 - __bfloat162float(h0), l1 = v1 - __bfloat162float(h1);
  int kt = kp >> 3;
  int bl = (n & 7) * 4 + (kp & 3);
  int j = (kp >> 2) & 1;
  int slot = B_FRAG(kt, n >> 3, bl, j);
  fh[slot] = pack_bf16(__bfloat162float(h0), __bfloat162float(h1));
  fl[slot] = pack_bf16(l0, l1);
}

// ---------------- wide GEMM via mma.sync bf16x3 ----------------

template <bool FUSE>
__global__ __launch_bounds__(256, 2)
void k_gemm_mma(const float* __restrict__ A, const uint32_t* __restrict__ Bh,
                const uint32_t* __restrict__ Bl, const float* __restrict__ bias,
                int M) {
  extern __shared__ uint32_t sm[];
  uint32_t* sAh = sm;        // 8192 u32 (32 KB)
  uint32_t* sAl = sm + 8192;

  const int tid = threadIdx.x;
  const int wid = tid >> 5;
  const int lane = tid & 31;
  const int bm = blockIdx.x * 128;

  // ---- A: load fp32 [m][k] (FUSE: relu(a*dinv+bias)), split, write frags ----
#pragma unroll
  for (int it = 0; it < 32; it++) {
    int idx = it * 256 + tid;
    int m = idx >> 6;
    int kp = idx & 63;  // k = 2*kp
    int arow = bm + m;
    float2 v = make_float2(0.f, 0.f);
    if (arow < M) {
      v = *(const float2*)(A + (size_t)arow * 128 + 2 * kp);
      if (FUSE) {
        float s = g_dinv[arow];
        float2 c = *(const float2*)(bias + 2 * kp);
        v.x = fmaxf(v.x * s + c.x, 0.f);
        v.y = fmaxf(v.y * s + c.y, 0.f);
      }
    }
    __nv_bfloat16 h0 = __float2bfloat16(v.x), h1 = __float2bfloat16(v.y);
    float l0 = v.x - __bfloat162float(h0), l1 = v.y - __bfloat162float(h1);
    int r = m & 15, mt = m >> 4, kt = kp >> 3;
    int al = (r & 7) * 4 + (kp & 3);
    int j = (r >> 3) + ((kp >> 2) & 1) * 2;
    int slot = A_FRAG(mt, kt, al, j);
    sAh[slot] = pack_bf16(__bfloat162float(h0), __bfloat162float(h1));
    sAl[slot] = pack_bf16(l0, l1);
  }
  __syncthreads();

  // ---- MMA mainloop: warp tile 32(m) x 64(n); 4 m-warps x 2 n-warps ----
  const int mw = wid & 3;
  const int nw = wid >> 2;

  float c[2][8][4];
#pragma unroll
  for (int mi = 0; mi < 2; mi++)
#pragma unroll
    for (int nt = 0; nt < 8; nt++)
#pragma unroll
      for (int q = 0; q < 4; q++) c[mi][nt][q] = 0.f;

#pragma unroll
  for (int kt = 0; kt < 8; kt++) {
    uint32_t ah[2][4], al_[2][4];
#pragma unroll
    for (int mi = 0; mi < 2; mi++) {
      *(uint4*)ah[mi]  = *(const uint4*)&sAh[A_FRAG(mw * 2 + mi, kt, lane, 0)];
      *(uint4*)al_[mi] = *(const uint4*)&sAl[A_FRAG(mw * 2 + mi, kt, lane, 0)];
    }
#pragma unroll
    for (int nh = 0; nh < 2; nh++) {
      uint32_t bh[4][2], bl_[4][2];
#pragma unroll
      for (int nt = 0; nt < 4; nt++) {
        int ntile = nw * 8 + nh * 4 + nt;
        *(uint2*)bh[nt]  = __ldg((const uint2*)&Bh[B_FRAG(kt, ntile, lane, 0)]);
        *(uint2*)bl_[nt] = __ldg((const uint2*)&Bl[B_FRAG(kt, ntile, lane, 0)]);
      }
#pragma unroll
      for (int mi = 0; mi < 2; mi++)
#pragma unroll
        for (int nt = 0; nt < 4; nt++) {
          float* cc = c[mi][nh * 4 + nt];
          mma_bf16(cc, ah[mi], bh[nt]);   // Ah*Bh
          mma_bf16(cc, ah[mi], bl_[nt]);  // Ah*Bl
          mma_bf16(cc, al_[mi], bh[nt]);  // Al*Bh
        }
    }
  }

  // ---- epilogue: g = acc * dinv[row] ----
#pragma unroll
  for (int mi = 0; mi < 2; mi++) {
    int r0 = bm + mw * 32 + mi * 16 + (lane >> 2);
    int r1 = r0 + 8;
    float s0 = (r0 < M) ? g_dinv[r0] : 0.f;
    float s1 = (r1 < M) ? g_dinv[r1] : 0.f;
#pragma unroll
    for (int nt = 0; nt < 8; nt++) {
      int col = nw * 64 + nt * 8 + (lane & 3) * 2;
      if (r0 < M)
        *(float2*)(g_g + (size_t)r0 * 128 + col) =
            make_float2(c[mi][nt][0] * s0, c[mi][nt][1] * s0);
      if (r1 < M)
        *(float2*)(g_g + (size_t)r1 * 128 + col) =
            make_float2(c[mi][nt][2] * s1, c[mi][nt][3] * s1);
    }
  }
}

// ---------------- narrow GEMM (D=40, TN=64, FFMA2) ----------------

__global__ __launch_bounds__(256, 2)
void k_gemm_narrow(const float* __restrict__ A, const float* __restrict__ B,
                   const float* __restrict__ bias, int M, int D) {
  constexpr int TN = 64;
  __shared__ float As[2][8][128];
  __shared__ float Bs[2][8][TN];

  const int tid = threadIdx.x;
  const int bm  = blockIdx.x * 128;
  const int tx  = tid & 15;
  const int ty  = tid >> 4;

  const int aRow = tid >> 1;
  const int aCol = (tid & 1) * 4;
  const int arow = bm + aRow;
  const bool aIn = arow < M;
  const float sA = aIn ? g_dinv[arow] : 0.0f;
  const float* Aptr = A + (size_t)arow * 128 + aCol;

  const int bRow = tid / (TN / 4);
  const int bCol = (tid % (TN / 4)) * 4;
  const bool bThread = tid < 2 * TN;
  const bool bIn = bThread && (bCol < D);

  unsigned long long acc[8][2];
#pragma unroll
  for (int i = 0; i < 8; i++) { acc[i][0] = 0ull; acc[i][1] = 0ull; }

  const float4 zero4 = make_float4(0.f, 0.f, 0.f, 0.f);

#define NLOAD_A(k0, av)                                             \
  do {                                                              \
    av = aIn ? *(const float4*)(Aptr + (k0)) : zero4;               \
    float4 c = aIn ? *(const float4*)(bias + (k0) + aCol) : zero4;  \
    av.x = fmaxf(av.x * sA + c.x, 0.f);                             \
    av.y = fmaxf(av.y * sA + c.y, 0.f);                             \
    av.z = fmaxf(av.z * sA + c.z, 0.f);                             \
    av.w = fmaxf(av.w * sA + c.w, 0.f);                             \
  } while (0)

#define NSTORE(bi, av, bv)                                          \
  do {                                                              \
    As[bi][aCol + 0][aRow] = av.x;                                  \
    As[bi][aCol + 1][aRow] = av.y;                                  \
    As[bi][aCol + 2][aRow] = av.z;                                  \
    As[bi][aCol + 3][aRow] = av.w;                                  \
    if (bThread) *(float4*)&Bs[bi][bRow][bCol] = bv;                \
  } while (0)

  {
    float4 av, bv;
    NLOAD_A(0, av);
    bv = bIn ? *(const float4*)(B + (size_t)bRow * D + bCol) : zero4;
    NSTORE(0, av, bv);
  }
  __syncthreads();

  int buf = 0;
  for (int k0 = 8; k0 <= 128; k0 += 8) {
    float4 av, bv;
    if (k0 < 128) {
      NLOAD_A(k0, av);
      bv = bIn ? *(const float4*)(B + (size_t)(k0 + bRow) * D + bCol) : zero4;
    }
#pragma unroll
    for (int kk = 0; kk < 8; kk++) {
      float a[8];
      *(float4*)(a)     = *(const float4*)&As[buf][kk][ty * 8];
      *(float4*)(a + 4) = *(const float4*)&As[buf][kk][ty * 8 + 4];
      ulonglong2 bb = *(const ulonglong2*)&Bs[buf][kk][tx * 4];
#pragma unroll
      for (int i = 0; i < 8; i++) {
        unsigned long long a2;
        asm("mov.b64 %0, {%1, %1};" : "=l"(a2) : "f"(a[i]));
        asm("fma.rn.f32x2 %0, %1, %2, %0;" : "+l"(acc[i][0]) : "l"(a2), "l"(bb.x));
        asm("fma.rn.f32x2 %0, %1, %2, %0;" : "+l"(acc[i][1]) : "l"(a2), "l"(bb.y));
      }
    }
    if (k0 < 128) {
      NSTORE(buf ^ 1, av, bv);
      __syncthreads();
      buf ^= 1;
    }
  }
#undef NLOAD_A
#undef NSTORE

#pragma unroll
  for (int i = 0; i < 8; i++) {
    int r = bm + ty * 8 + i;
    if (r >= M) continue;
    int col = tx * 4;
    if (col >= D) continue;
    float s = g_dinv[r];
    float x0, x1, x2, x3;
    asm("mov.b64 {%0, %1}, %2;" : "=f"(x0), "=f"(x1) : "l"(acc[i][0]));
    asm("mov.b64 {%0, %1}, %2;" : "=f"(x2), "=f"(x3) : "l"(acc[i][1]));
    *(float4*)(g_g + (size_t)r * D + col) =
        make_float4(x0 * s, x1 * s, x2 * s, x3 * s);
  }
}

// ---------------- CSR gather: agg[d] = g[d] + sum g[src] ----------------

__global__ void k_gather(int n) {  // D = 128, warp per node
  int w    = (blockIdx.x * blockDim.x + threadIdx.x) >> 5;
  int lane = threadIdx.x & 31;
  if (w >= n) return;
  int beg = __ldg(g_rowptr + w);
  int end = __ldg(g_rowptr + w + 1);
  float4 acc = *(const float4*)(g_g + (size_t)w * 128 + lane * 4);
  for (int e = beg; e < end; e++) {
    int s = __ldg(g_eidx + e);
    float4 v = __ldg((const float4*)(g_g + (size_t)s * 128 + lane * 4));
    acc.x += v.x; acc.y += v.y; acc.z += v.z; acc.w += v.w;
  }
  *(float4*)(g_agg + (size_t)w * 128 + lane * 4) = acc;
}

// last layer (D=40): gather + finalize fused, half-warp per node, write d_out.
__global__ void k_gather_out(const float* __restrict__ bias,
                             float* __restrict__ out, int n, int D) {
  int t    = blockIdx.x * blockDim.x + threadIdx.x;
  int half = t >> 4;
  int lane = t & 15;
  if (half >= n) return;
  int node = half;
  int c = lane * 4;
  if (c >= D) return;
  int beg = __ldg(g_rowptr + node);
  int end = __ldg(g_rowptr + node + 1);
  float4 acc = *(const float4*)(g_g + (size_t)node * D + c);
  for (int e = beg; e < end; e++) {
    int s = __ldg(g_eidx + e);
    float4 v = __ldg((const float4*)(g_g + (size_t)s * D + c));
    acc.x += v.x; acc.y += v.y; acc.z += v.z; acc.w += v.w;
  }
  float sc = g_dinv[node];
  float4 b = *(const float4*)(bias + c);
  acc.x = acc.x * sc + b.x;
  acc.y = acc.y * sc + b.y;
  acc.z = acc.z * sc + b.z;
  acc.w = acc.w * sc + b.w;
  *(float4*)(out + (size_t)node * D + c) = acc;
}

// ---------------- host launcher ----------------

extern "C" void kernel_launch(void* const* d_in, const int* in_sizes, int n_in,
                              void* d_out, int out_size) {
  const float* x  = (const float*)d_in[0];
  const int*   ei = (const int*)d_in[1];
  const float* W[4] = {(const float*)d_in[2], (const float*)d_in[4],
                       (const float*)d_in[6], (const float*)d_in[8]};
  const float* b[4] = {(const float*)d_in[3], (const float*)d_in[5],
                       (const float*)d_in[7], (const float*)d_in[9]};

  int M = in_sizes[0] / FD;  // 100000
  int E = in_sizes[1] / 2;   // 500000
  const int* src = ei;
  const int* dst = ei + E;

  float* agg;
  cudaGetSymbolAddress((void**)&agg, g_agg);
  uint32_t *wfh, *wfl;
  cudaGetSymbolAddress((void**)&wfh, g_wfh);
  cudaGetSymbolAddress((void**)&wfl, g_wfl);

  const int SMEM = 65536;  // A fragments only (hi+lo)
  cudaFuncSetAttribute(k_gemm_mma<false>,
                       cudaFuncAttributeMaxDynamicSharedMemorySize, SMEM);
  cudaFuncSetAttribute(k_gemm_mma<true>,
                       cudaFuncAttributeMaxDynamicSharedMemorySize, SMEM);

  int nscan = (M + SCAN_B - 1) / SCAN_B;  // 196
  int GB = (M + 127) / 128;               // 782
  int gatherB = (M * 32 + 255) / 256;     // 12500

  // degree
  k_zero_cnt<<<(M + 255) / 256, 256>>>(M);
  k_count<<<(E + 255) / 256, 256>>>(dst, E);
  k_deg_rsqrt<<<(M + 255) / 256, 256>>>(M);
  // W fragment prep (once per wide layer)
  for (int l = 0; l < 3; l++)
    k_wprep<<<32, 256>>>(W[l], wfh + l * 8192, wfl + l * 8192);
  // scan prefix
  k_scan1<<<nscan, SCAN_B>>>(M);
  k_scan2<<<1, 256>>>(nscan);
  // layer-0 GEMM (needs only dinv + frags)
  k_gemm_mma<false><<<GB, 256, SMEM>>>(x, wfh, wfl, b[0], M);
  // finish CSR
  k_scan3<<<nscan, SCAN_B>>>(M);
  k_fill<<<(E + 255) / 256, 256>>>(src, dst, E);

  // layer 0 aggregate
  k_gather<<<gatherB, 256>>>(M);
  // layers 1-2
  k_gemm_mma<true><<<GB, 256, SMEM>>>(agg, wfh + 8192, wfl + 8192, b[0], M);
  k_gather<<<gatherB, 256>>>(M);
  k_gemm_mma<true><<<GB, 256, SMEM>>>(agg, wfh + 16384, wfl + 16384, b[1], M);
  k_gather<<<gatherB, 256>>>(M);
  // layer 3: D = 40; gather+finalize fused -> d_out
  k_gemm_narrow<<<GB, 256>>>(agg, W[3], b[2], M, 40);
  k_gather_out<<<(M * 16 + 255) / 256, 256>>>(b[3], (float*)d_out, M, 40);
}

// round 12
// speedup vs baseline: 2.1350x; 1.0872x over previous
#include <cuda_runtime.h>
#include <cuda_bf16.h>
#include <cstdint>

// GCN, 4 layers: h' = relu( D^-1/2 (A+I) D^-1/2 (h W) + b )
// ALL GEMMs on tensor cores via mma.sync bf16x3 split (D = AhBh+AhBl+AlBh,
// fp32 accum; ~5e-6 rel err). W fragments pre-converted once per layer
// (k_wprep) into global; GEMM loads them via __ldg (L1/L2-resident).
// Narrow layer (->40) uses the same kernel with NT=8 (64 cols, zero-padded).
// agg[d] = g[d] + sum_{(s->d)} g[s] via CSR gather (4-wide unrolled edge
// loop for MLP); relu(agg*dinv+b) of layer l fused into layer l+1's A load.

#define NN 100000
#define EE 500000
#define FD 128

__device__ float g_dinv[NN];
__device__ float g_g[(size_t)NN * FD];
__device__ float g_agg[(size_t)NN * FD];
// CSR (dst-major)
__device__ int g_cnt[NN];
__device__ int g_rowptr[NN + 1];
__device__ int g_fill[NN];
__device__ int g_eidx[EE];
__device__ int g_bsums[256];
// pre-converted W fragments (hi/lo): 3 wide layers x 8192, narrow x 4096
__device__ uint32_t g_wfh[3][8192];
__device__ uint32_t g_wfl[3][8192];
__device__ uint32_t g_w3h[4096];
__device__ uint32_t g_w3l[4096];

// ---------------- degree + CSR build ----------------

__global__ void k_zero_cnt(int n) {
  int i = blockIdx.x * blockDim.x + threadIdx.x;
  if (i < n) g_cnt[i] = 0;
}
__global__ void k_count(const int* __restrict__ dst, int e) {
  int i = blockIdx.x * blockDim.x + threadIdx.x;
  if (i < e) atomicAdd(&g_cnt[dst[i]], 1);
}
__global__ void k_deg_rsqrt(int n) {
  int i = blockIdx.x * blockDim.x + threadIdx.x;
  if (i < n) g_dinv[i] = rsqrtf((float)(1 + g_cnt[i]));  // +1 self loop
}

#define SCAN_B 512
__global__ void k_scan1(int n) {
  __shared__ int sm[SCAN_B];
  int i = blockIdx.x * SCAN_B + threadIdx.x;
  sm[threadIdx.x] = (i < n) ? g_cnt[i] : 0;
  __syncthreads();
  for (int off = 1; off < SCAN_B; off <<= 1) {
    int t = (threadIdx.x >= off) ? sm[threadIdx.x - off] : 0;
    __syncthreads();
    sm[threadIdx.x] += t;
    __syncthreads();
  }
  if (i < n) g_rowptr[i + 1] = sm[threadIdx.x];
  if (threadIdx.x == SCAN_B - 1) g_bsums[blockIdx.x] = sm[threadIdx.x];
  if (i == 0) g_rowptr[0] = 0;
}
__global__ void k_scan2(int nb) {
  __shared__ int sm[256];
  sm[threadIdx.x] = (threadIdx.x < nb) ? g_bsums[threadIdx.x] : 0;
  __syncthreads();
  for (int off = 1; off < 256; off <<= 1) {
    int t = (threadIdx.x >= off) ? sm[threadIdx.x - off] : 0;
    __syncthreads();
    sm[threadIdx.x] += t;
    __syncthreads();
  }
  if (threadIdx.x < nb) g_bsums[threadIdx.x] = sm[threadIdx.x];
}
__global__ void k_scan3(int n) {  // add carried offsets; also init g_fill
  int i = blockIdx.x * SCAN_B + threadIdx.x;
  if (i < n) {
    int v = g_rowptr[i + 1];
    if (blockIdx.x > 0) v += g_bsums[blockIdx.x - 1];
    g_rowptr[i + 1] = v;
    if (i + 1 < n) g_fill[i + 1] = v;
    if (i == 0) g_fill[0] = 0;
  }
}
__global__ void k_fill(const int* __restrict__ src, const int* __restrict__ dst,
                       int e) {
  int i = blockIdx.x * blockDim.x + threadIdx.x;
  if (i < e) {
    int p = atomicAdd(&g_fill[dst[i]], 1);
    g_eidx[p] = src[i];
  }
}

// ---------------- fragment layout ----------------
//   A: [mtile 8][ktile 8][lane 32][j 4]        (m16k16 row-major A fragment)
//   B: [ktile 8][ntile NT][lane 32][j 2]       (k16n8 col-major B fragment)
#define A_FRAG(mt, kt, lane, j) ((((mt) * 8 + (kt)) * 32 + (lane)) * 4 + (j))

__device__ __forceinline__ uint32_t pack_bf16(float x, float y) {
  __nv_bfloat162 p = __floats2bfloat162_rn(x, y);  // x -> low half
  return *(uint32_t*)&p;
}

__device__ __forceinline__ void mma_bf16(float* c, const uint32_t* a,
                                         const uint32_t* b) {
  asm volatile(
      "mma.sync.aligned.m16n8k16.row.col.f32.bf16.bf16.f32 "
      "{%0,%1,%2,%3}, {%4,%5,%6,%7}, {%8,%9}, {%0,%1,%2,%3};"
      : "+f"(c[0]), "+f"(c[1]), "+f"(c[2]), "+f"(c[3])
      : "r"(a[0]), "r"(a[1]), "r"(a[2]), "r"(a[3]), "r"(b[0]), "r"(b[1]));
}

// per-layer W -> fragment conversion. W is [128][D]; cols >= D zero-padded
// up to NT*8. total threads = NT*8*64.
__global__ void k_wprep(const float* __restrict__ W, uint32_t* __restrict__ fh,
                        uint32_t* __restrict__ fl, int D, int NT) {
  int idx = blockIdx.x * blockDim.x + threadIdx.x;
  int ncols = NT * 8;
  if (idx >= ncols * 64) return;
  int n = idx % ncols;
  int kp = idx / ncols;  // k pair index 0..63
  float v0 = 0.f, v1 = 0.f;
  if (n < D) {
    v0 = W[(size_t)(2 * kp) * D + n];
    v1 = W[(size_t)(2 * kp + 1) * D + n];
  }
  __nv_bfloat16 h0 = __float2bfloat16(v0), h1 = __float2bfloat16(v1);
  float l0 = v0 - __bfloat162float(h0), l1 = v1 - __bfloat162float(h1);
  int kt = kp >> 3;
  int lane = (n & 7) * 4 + (kp & 3);
  int j = (kp >> 2) & 1;
  int slot = (((kt * NT) + (n >> 3)) * 32 + lane) * 2 + j;
  fh[slot] = pack_bf16(__bfloat162float(h0), __bfloat162float(h1));
  fl[slot] = pack_bf16(l0, l1);
}

// ---------------- GEMM via mma.sync bf16x3 ----------------
// Block tile 128(m) x NT*8(n), K=128. 8 warps: 4 m-warps x 2 n-warps.
// Output g = acc * dinv[row] -> g_g with row stride DOUT (cols >= DOUT dropped).

template <bool FUSE, int NT, int DOUT>
__global__ __launch_bounds__(256, 2)
void k_gemm_mma(const float* __restrict__ A, const uint32_t* __restrict__ Bh,
                const uint32_t* __restrict__ Bl, const float* __restrict__ bias,
                int M) {
  extern __shared__ uint32_t sm[];
  uint32_t* sAh = sm;  // 8192 u32 (32 KB)
  uint32_t* sAl = sm + 8192;

  const int tid = threadIdx.x;
  const int wid = tid >> 5;
  const int lane = tid & 31;
  const int bm = blockIdx.x * 128;
  constexpr int WNT = NT / 2;  // ntiles per n-warp

  // ---- A: load fp32 [m][128] (FUSE: relu(a*dinv+bias)), split, write frags --
#pragma unroll
  for (int it = 0; it < 32; it++) {
    int idx = it * 256 + tid;
    int m = idx >> 6;
    int kp = idx & 63;  // k = 2*kp
    int arow = bm + m;
    float2 v = make_float2(0.f, 0.f);
    if (arow < M) {
      v = *(const float2*)(A + (size_t)arow * 128 + 2 * kp);
      if (FUSE) {
        float s = g_dinv[arow];
        float2 c = *(const float2*)(bias + 2 * kp);
        v.x = fmaxf(v.x * s + c.x, 0.f);
        v.y = fmaxf(v.y * s + c.y, 0.f);
      }
    }
    __nv_bfloat16 h0 = __float2bfloat16(v.x), h1 = __float2bfloat16(v.y);
    float l0 = v.x - __bfloat162float(h0), l1 = v.y - __bfloat162float(h1);
    int r = m & 15, mt = m >> 4, kt = kp >> 3;
    int al = (r & 7) * 4 + (kp & 3);
    int j = (r >> 3) + ((kp >> 2) & 1) * 2;
    int slot = A_FRAG(mt, kt, al, j);
    sAh[slot] = pack_bf16(__bfloat162float(h0), __bfloat162float(h1));
    sAl[slot] = pack_bf16(l0, l1);
  }
  __syncthreads();

  // ---- MMA mainloop ----
  const int mw = wid & 3;
  const int nw = wid >> 2;

  float c[2][WNT][4];
#pragma unroll
  for (int mi = 0; mi < 2; mi++)
#pragma unroll
    for (int nt = 0; nt < WNT; nt++)
#pragma unroll
      for (int q = 0; q < 4; q++) c[mi][nt][q] = 0.f;

#pragma unroll
  for (int kt = 0; kt < 8; kt++) {
    uint32_t ah[2][4], al_[2][4];
#pragma unroll
    for (int mi = 0; mi < 2; mi++) {
      *(uint4*)ah[mi]  = *(const uint4*)&sAh[A_FRAG(mw * 2 + mi, kt, lane, 0)];
      *(uint4*)al_[mi] = *(const uint4*)&sAl[A_FRAG(mw * 2 + mi, kt, lane, 0)];
    }
#pragma unroll
    for (int nh = 0; nh < WNT / 4; nh++) {
      uint32_t bh[4][2], bl_[4][2];
#pragma unroll
      for (int nt = 0; nt < 4; nt++) {
        int ntile = nw * WNT + nh * 4 + nt;
        int slot = ((kt * NT + ntile) * 32 + lane) * 2;
        *(uint2*)bh[nt]  = __ldg((const uint2*)&Bh[slot]);
        *(uint2*)bl_[nt] = __ldg((const uint2*)&Bl[slot]);
      }
#pragma unroll
      for (int mi = 0; mi < 2; mi++)
#pragma unroll
        for (int nt = 0; nt < 4; nt++) {
          float* cc = c[mi][nh * 4 + nt];
          mma_bf16(cc, ah[mi], bh[nt]);   // Ah*Bh
          mma_bf16(cc, ah[mi], bl_[nt]);  // Ah*Bl
          mma_bf16(cc, al_[mi], bh[nt]);  // Al*Bh
        }
    }
  }

  // ---- epilogue: g = acc * dinv[row] (row stride DOUT) ----
#pragma unroll
  for (int mi = 0; mi < 2; mi++) {
    int r0 = bm + mw * 32 + mi * 16 + (lane >> 2);
    int r1 = r0 + 8;
    float s0 = (r0 < M) ? g_dinv[r0] : 0.f;
    float s1 = (r1 < M) ? g_dinv[r1] : 0.f;
#pragma unroll
    for (int nt = 0; nt < WNT; nt++) {
      int col = (nw * WNT + nt) * 8 + (lane & 3) * 2;
      if (col >= DOUT) continue;
      if (r0 < M)
        *(float2*)(g_g + (size_t)r0 * DOUT + col) =
            make_float2(c[mi][nt][0] * s0, c[mi][nt][1] * s0);
      if (r1 < M)
        *(float2*)(g_g + (size_t)r1 * DOUT + col) =
            make_float2(c[mi][nt][2] * s1, c[mi][nt][3] * s1);
    }
  }
}

// ---------------- CSR gather: agg[d] = g[d] + sum g[src] ----------------
// 4-wide unrolled edge loop for memory-level parallelism.

__global__ void k_gather(int n) {  // D = 128, warp per node
  int w    = (blockIdx.x * blockDim.x + threadIdx.x) >> 5;
  int lane = threadIdx.x & 31;
  if (w >= n) return;
  int beg = __ldg(g_rowptr + w);
  int end = __ldg(g_rowptr + w + 1);
  float4 acc = *(const float4*)(g_g + (size_t)w * 128 + lane * 4);
  int e = beg;
  for (; e + 4 <= end; e += 4) {
    int s0 = __ldg(g_eidx + e);
    int s1 = __ldg(g_eidx + e + 1);
    int s2 = __ldg(g_eidx + e + 2);
    int s3 = __ldg(g_eidx + e + 3);
    float4 v0 = __ldg((const float4*)(g_g + (size_t)s0 * 128 + lane * 4));
    float4 v1 = __ldg((const float4*)(g_g + (size_t)s1 * 128 + lane * 4));
    float4 v2 = __ldg((const float4*)(g_g + (size_t)s2 * 128 + lane * 4));
    float4 v3 = __ldg((const float4*)(g_g + (size_t)s3 * 128 + lane * 4));
    acc.x += v0.x; acc.y += v0.y; acc.z += v0.z; acc.w += v0.w;
    acc.x += v1.x; acc.y += v1.y; acc.z += v1.z; acc.w += v1.w;
    acc.x += v2.x; acc.y += v2.y; acc.z += v2.z; acc.w += v2.w;
    acc.x += v3.x; acc.y += v3.y; acc.z += v3.z; acc.w += v3.w;
  }
  for (; e < end; e++) {
    int s = __ldg(g_eidx + e);
    float4 v = __ldg((const float4*)(g_g + (size_t)s * 128 + lane * 4));
    acc.x += v.x; acc.y += v.y; acc.z += v.z; acc.w += v.w;
  }
  *(float4*)(g_agg + (size_t)w * 128 + lane * 4) = acc;
}

// last layer (D=40): gather + finalize fused, half-warp per node, write d_out.
__global__ void k_gather_out(const float* __restrict__ bias,
                             float* __restrict__ out, int n, int D) {
  int t    = blockIdx.x * blockDim.x + threadIdx.x;
  int node = t >> 4;
  int lane = t & 15;
  if (node >= n) return;
  int c = lane * 4;
  if (c >= D) return;
  int beg = __ldg(g_rowptr + node);
  int end = __ldg(g_rowptr + node + 1);
  float4 acc = *(const float4*)(g_g + (size_t)node * D + c);
  int e = beg;
  for (; e + 4 <= end; e += 4) {
    int s0 = __ldg(g_eidx + e);
    int s1 = __ldg(g_eidx + e + 1);
    int s2 = __ldg(g_eidx + e + 2);
    int s3 = __ldg(g_eidx + e + 3);
    float4 v0 = __ldg((const float4*)(g_g + (size_t)s0 * D + c));
    float4 v1 = __ldg((const float4*)(g_g + (size_t)s1 * D + c));
    float4 v2 = __ldg((const float4*)(g_g + (size_t)s2 * D + c));
    float4 v3 = __ldg((const float4*)(g_g + (size_t)s3 * D + c));
    acc.x += v0.x; acc.y += v0.y; acc.z += v0.z; acc.w += v0.w;
    acc.x += v1.x; acc.y += v1.y; acc.z += v1.z; acc.w += v1.w;
    acc.x += v2.x; acc.y += v2.y; acc.z += v2.z; acc.w += v2.w;
    acc.x += v3.x; acc.y += v3.y; acc.z += v3.z; acc.w += v3.w;
  }
  for (; e < end; e++) {
    int s = __ldg(g_eidx + e);
    float4 v = __ldg((const float4*)(g_g + (size_t)s * D + c));
    acc.x += v.x; acc.y += v.y; acc.z += v.z; acc.w += v.w;
  }
  float sc = g_dinv[node];
  float4 b = *(const float4*)(bias + c);
  acc.x = acc.x * sc + b.x;
  acc.y = acc.y * sc + b.y;
  acc.z = acc.z * sc + b.z;
  acc.w = acc.w * sc + b.w;
  *(float4*)(out + (size_t)node * D + c) = acc;
}

// ---------------- host launcher ----------------

extern "C" void kernel_launch(void* const* d_in, const int* in_sizes, int n_in,
                              void* d_out, int out_size) {
  const float* x  = (const float*)d_in[0];
  const int*   ei = (const int*)d_in[1];
  const float* W[4] = {(const float*)d_in[2], (const float*)d_in[4],
                       (const float*)d_in[6], (const float*)d_in[8]};
  const float* b[4] = {(const float*)d_in[3], (const float*)d_in[5],
                       (const float*)d_in[7], (const float*)d_in[9]};

  int M = in_sizes[0] / FD;  // 100000
  int E = in_sizes[1] / 2;   // 500000
  const int* src = ei;
  const int* dst = ei + E;

  float* agg;
  cudaGetSymbolAddress((void**)&agg, g_agg);
  uint32_t *wfh, *wfl, *w3h, *w3l;
  cudaGetSymbolAddress((void**)&wfh, g_wfh);
  cudaGetSymbolAddress((void**)&wfl, g_wfl);
  cudaGetSymbolAddress((void**)&w3h, g_w3h);
  cudaGetSymbolAddress((void**)&w3l, g_w3l);

  const int SMEM = 65536;  // A fragments only (hi+lo)
  cudaFuncSetAttribute((const void*)k_gemm_mma<false, 16, 128>,
                       cudaFuncAttributeMaxDynamicSharedMemorySize, SMEM);
  cudaFuncSetAttribute((const void*)k_gemm_mma<true, 16, 128>,
                       cudaFuncAttributeMaxDynamicSharedMemorySize, SMEM);
  cudaFuncSetAttribute((const void*)k_gemm_mma<true, 8, 40>,
                       cudaFuncAttributeMaxDynamicSharedMemorySize, SMEM);

  int nscan = (M + SCAN_B - 1) / SCAN_B;  // 196
  int GB = (M + 127) / 128;               // 782
  int gatherB = (M * 32 + 255) / 256;     // 12500

  // degree
  k_zero_cnt<<<(M + 255) / 256, 256>>>(M);
  k_count<<<(E + 255) / 256, 256>>>(dst, E);
  k_deg_rsqrt<<<(M + 255) / 256, 256>>>(M);
  // W fragment prep (once per layer)
  for (int l = 0; l < 3; l++)
    k_wprep<<<32, 256>>>(W[l], wfh + l * 8192, wfl + l * 8192, 128, 16);
  k_wprep<<<16, 256>>>(W[3], w3h, w3l, 40, 8);
  // scan prefix
  k_scan1<<<nscan, SCAN_B>>>(M);
  k_scan2<<<1, 256>>>(nscan);
  // layer-0 GEMM (needs only dinv + frags)
  k_gemm_mma<false, 16, 128><<<GB, 256, SMEM>>>(x, wfh, wfl, b[0], M);
  // finish CSR
  k_scan3<<<nscan, SCAN_B>>>(M);
  k_fill<<<(E + 255) / 256, 256>>>(src, dst, E);

  // layer 0 aggregate
  k_gather<<<gatherB, 256>>>(M);
  // layers 1-2
  k_gemm_mma<true, 16, 128><<<GB, 256, SMEM>>>(agg, wfh + 8192, wfl + 8192,
                                               b[0], M);
  k_gather<<<gatherB, 256>>>(M);
  k_gemm_mma<true, 16, 128><<<GB, 256, SMEM>>>(agg, wfh + 16384, wfl + 16384,
                                               b[1], M);
  k_gather<<<gatherB, 256>>>(M);
  // layer 3: D = 40 on mma (NT=8, cols 40..63 zero-padded)
  k_gemm_mma<true, 8, 40><<<GB, 256, SMEM>>>(agg, w3h, w3l, b[2], M);
  k_gather_out<<<(M * 16 + 255) / 256, 256>>>(b[3], (float*)d_out, M, 40);
}

// round 13
// speedup vs baseline: 2.2400x; 1.0492x over previous
#include <cuda_runtime.h>
#include <cuda_bf16.h>
#include <cstdint>

// GCN, 4 layers: h' = relu( D^-1/2 (A+I) D^-1/2 (h W) + b )
// All GEMMs on mma.sync bf16x3 (D = AhBh+AhBl+AlBh, fp32 accum, ~6e-6 err).
// W fragments pre-converted once (k_wprep_all). The CSR gather applies
// relu(agg*dinv+bias), splits to bf16 hi/lo and writes the NEXT layer's
// A-FRAGMENTS directly to global -> follow-on GEMMs (k_gemm_frag) have no
// smem / no syncthreads / no convert phase: pure LDG + MMA.
// Layer 0 GEMM keeps the convert-in-kernel path (reads raw x).

#define NN 100000
#define EE 500000
#define FD 128
#define NBLK 782  // ceil(NN/128)

__device__ float g_dinv[NN];
__device__ float g_g[(size_t)NN * FD];
// CSR (dst-major)
__device__ int g_cnt[NN];
__device__ int g_rowptr[NN + 1];
__device__ int g_fill[NN];
__device__ int g_eidx[EE];
__device__ int g_bsums[256];
// W fragments (hi/lo): 3 wide layers x 8192, narrow 4096
__device__ uint32_t g_wfh[3][8192];
__device__ uint32_t g_wfl[3][8192];
__device__ uint32_t g_w3h[4096];
__device__ uint32_t g_w3l[4096];
// A fragments written by the gather (zero-init covers pad rows)
__device__ uint32_t g_afh[(size_t)NBLK * 8192];
__device__ uint32_t g_afl[(size_t)NBLK * 8192];

// ---------------- degree + CSR build ----------------

__global__ void k_zero_cnt(int n) {
  int i = blockIdx.x * blockDim.x + threadIdx.x;
  if (i < n) g_cnt[i] = 0;
}
__global__ void k_count(const int* __restrict__ dst, int e) {
  int i = blockIdx.x * blockDim.x + threadIdx.x;
  if (i < e) atomicAdd(&g_cnt[dst[i]], 1);
}

#define SCAN_B 512
__global__ void k_scan1(int n) {  // block scan -> rowptr[i+1]; also dinv
  __shared__ int sm[SCAN_B];
  int i = blockIdx.x * SCAN_B + threadIdx.x;
  int cnt = (i < n) ? g_cnt[i] : 0;
  if (i < n) g_dinv[i] = rsqrtf((float)(1 + cnt));  // +1 self loop
  sm[threadIdx.x] = cnt;
  __syncthreads();
  for (int off = 1; off < SCAN_B; off <<= 1) {
    int t = (threadIdx.x >= off) ? sm[threadIdx.x - off] : 0;
    __syncthreads();
    sm[threadIdx.x] += t;
    __syncthreads();
  }
  if (i < n) g_rowptr[i + 1] = sm[threadIdx.x];
  if (threadIdx.x == SCAN_B - 1) g_bsums[blockIdx.x] = sm[threadIdx.x];
  if (i == 0) g_rowptr[0] = 0;
}
__global__ void k_scan2(int nb) {
  __shared__ int sm[256];
  sm[threadIdx.x] = (threadIdx.x < nb) ? g_bsums[threadIdx.x] : 0;
  __syncthreads();
  for (int off = 1; off < 256; off <<= 1) {
    int t = (threadIdx.x >= off) ? sm[threadIdx.x - off] : 0;
    __syncthreads();
    sm[threadIdx.x] += t;
    __syncthreads();
  }
  if (threadIdx.x < nb) g_bsums[threadIdx.x] = sm[threadIdx.x];
}
__global__ void k_scan3(int n) {  // add carried offsets; init g_fill
  int i = blockIdx.x * SCAN_B + threadIdx.x;
  if (i < n) {
    int v = g_rowptr[i + 1];
    if (blockIdx.x > 0) v += g_bsums[blockIdx.x - 1];
    g_rowptr[i + 1] = v;
    if (i + 1 < n) g_fill[i + 1] = v;
    if (i == 0) g_fill[0] = 0;
  }
}
__global__ void k_fill(const int* __restrict__ src, const int* __restrict__ dst,
                       int e) {
  int i = blockIdx.x * blockDim.x + threadIdx.x;
  if (i < e) {
    int p = atomicAdd(&g_fill[dst[i]], 1);
    g_eidx[p] = src[i];
  }
}

// ---------------- fragment layout ----------------
//   A: [mtile 8][ktile 8][lane 32][j 4]   (m16k16 row-major A fragment)
//   B: [ktile 8][ntile NT][lane 32][j 2]  (k16n8 col-major B fragment)
#define A_FRAG(mt, kt, lane, j) ((((mt) * 8 + (kt)) * 32 + (lane)) * 4 + (j))

__device__ __forceinline__ uint32_t pack_bf16(float x, float y) {
  __nv_bfloat162 p = __floats2bfloat162_rn(x, y);  // x -> low half
  return *(uint32_t*)&p;
}

__device__ __forceinline__ void mma_bf16(float* c, const uint32_t* a,
                                         const uint32_t* b) {
  asm volatile(
      "mma.sync.aligned.m16n8k16.row.col.f32.bf16.bf16.f32 "
      "{%0,%1,%2,%3}, {%4,%5,%6,%7}, {%8,%9}, {%0,%1,%2,%3};"
      : "+f"(c[0]), "+f"(c[1]), "+f"(c[2]), "+f"(c[3])
      : "r"(a[0]), "r"(a[1]), "r"(a[2]), "r"(a[3]), "r"(b[0]), "r"(b[1]));
}

// all-layer W -> fragment conversion (blockIdx.y = layer)
__global__ void k_wprep_all(const float* __restrict__ W0,
                            const float* __restrict__ W1,
                            const float* __restrict__ W2,
                            const float* __restrict__ W3) {
  int l = blockIdx.y;
  const float* W = (l == 0) ? W0 : (l == 1) ? W1 : (l == 2) ? W2 : W3;
  int D = (l < 3) ? 128 : 40;
  int NT = (l < 3) ? 16 : 8;
  uint32_t* fh = (l < 3) ? g_wfh[l] : g_w3h;
  uint32_t* fl = (l < 3) ? g_wfl[l] : g_w3l;
  int idx = blockIdx.x * blockDim.x + threadIdx.x;
  int ncols = NT * 8;
  if (idx >= ncols * 64) return;
  int n = idx % ncols;
  int kp = idx / ncols;  // k pair 0..63
  float v0 = 0.f, v1 = 0.f;
  if (n < D) {
    v0 = W[(size_t)(2 * kp) * D + n];
    v1 = W[(size_t)(2 * kp + 1) * D + n];
  }
  __nv_bfloat16 h0 = __float2bfloat16(v0), h1 = __float2bfloat16(v1);
  float l0 = v0 - __bfloat162float(h0), l1 = v1 - __bfloat162float(h1);
  int kt = kp >> 3;
  int lane = (n & 7) * 4 + (kp & 3);
  int j = (kp >> 2) & 1;
  int slot = (((kt * NT) + (n >> 3)) * 32 + lane) * 2 + j;
  fh[slot] = pack_bf16(__bfloat162float(h0), __bfloat162float(h1));
  fl[slot] = pack_bf16(l0, l1);
}

// ---------------- layer-0 GEMM (convert path, raw fp32 A) ----------------

__global__ __launch_bounds__(256, 2)
void k_gemm_l0(const float* __restrict__ A, const uint32_t* __restrict__ Bh,
               const uint32_t* __restrict__ Bl, int M) {
  extern __shared__ uint32_t sm[];
  uint32_t* sAh = sm;  // 8192 u32
  uint32_t* sAl = sm + 8192;

  const int tid = threadIdx.x;
  const int wid = tid >> 5;
  const int lane = tid & 31;
  const int bm = blockIdx.x * 128;

#pragma unroll
  for (int it = 0; it < 32; it++) {
    int idx = it * 256 + tid;
    int m = idx >> 6;
    int kp = idx & 63;
    int arow = bm + m;
    float2 v = make_float2(0.f, 0.f);
    if (arow < M) v = *(const float2*)(A + (size_t)arow * 128 + 2 * kp);
    __nv_bfloat16 h0 = __float2bfloat16(v.x), h1 = __float2bfloat16(v.y);
    float l0 = v.x - __bfloat162float(h0), l1 = v.y - __bfloat162float(h1);
    int r = m & 15, mt = m >> 4, kt = kp >> 3;
    int al = (r & 7) * 4 + (kp & 3);
    int j = (r >> 3) + ((kp >> 2) & 1) * 2;
    int slot = A_FRAG(mt, kt, al, j);
    sAh[slot] = pack_bf16(__bfloat162float(h0), __bfloat162float(h1));
    sAl[slot] = pack_bf16(l0, l1);
  }
  __syncthreads();

  const int mw = wid & 3;
  const int nw = wid >> 2;
  float c[2][8][4];
#pragma unroll
  for (int mi = 0; mi < 2; mi++)
#pragma unroll
    for (int nt = 0; nt < 8; nt++)
#pragma unroll
      for (int q = 0; q < 4; q++) c[mi][nt][q] = 0.f;

#pragma unroll
  for (int kt = 0; kt < 8; kt++) {
    uint32_t ah[2][4], al_[2][4];
#pragma unroll
    for (int mi = 0; mi < 2; mi++) {
      *(uint4*)ah[mi]  = *(const uint4*)&sAh[A_FRAG(mw * 2 + mi, kt, lane, 0)];
      *(uint4*)al_[mi] = *(const uint4*)&sAl[A_FRAG(mw * 2 + mi, kt, lane, 0)];
    }
#pragma unroll
    for (int nh = 0; nh < 2; nh++) {
      uint32_t bh[4][2], bl_[4][2];
#pragma unroll
      for (int nt = 0; nt < 4; nt++) {
        int ntile = nw * 8 + nh * 4 + nt;
        int slot = ((kt * 16 + ntile) * 32 + lane) * 2;
        *(uint2*)bh[nt]  = __ldg((const uint2*)&Bh[slot]);
        *(uint2*)bl_[nt] = __ldg((const uint2*)&Bl[slot]);
      }
#pragma unroll
      for (int mi = 0; mi < 2; mi++)
#pragma unroll
        for (int nt = 0; nt < 4; nt++) {
          float* cc = c[mi][nh * 4 + nt];
          mma_bf16(cc, ah[mi], bh[nt]);
          mma_bf16(cc, ah[mi], bl_[nt]);
          mma_bf16(cc, al_[mi], bh[nt]);
        }
    }
  }

#pragma unroll
  for (int mi = 0; mi < 2; mi++) {
    int r0 = bm + mw * 32 + mi * 16 + (lane >> 2);
    int r1 = r0 + 8;
    float s0 = (r0 < M) ? g_dinv[r0] : 0.f;
    float s1 = (r1 < M) ? g_dinv[r1] : 0.f;
#pragma unroll
    for (int nt = 0; nt < 8; nt++) {
      int col = (nw * 8 + nt) * 8 + (lane & 3) * 2;
      if (r0 < M)
        *(float2*)(g_g + (size_t)r0 * 128 + col) =
            make_float2(c[mi][nt][0] * s0, c[mi][nt][1] * s0);
      if (r1 < M)
        *(float2*)(g_g + (size_t)r1 * 128 + col) =
            make_float2(c[mi][nt][2] * s1, c[mi][nt][3] * s1);
    }
  }
}

// ---------------- fragment-input GEMM (layers 1..3): no smem, no sync ------

template <int NT, int DOUT>
__global__ __launch_bounds__(256, 2)
void k_gemm_frag(const uint32_t* __restrict__ Bh, const uint32_t* __restrict__ Bl,
                 int M) {
  const int tid = threadIdx.x;
  const int wid = tid >> 5;
  const int lane = tid & 31;
  const int bm = blockIdx.x * 128;
  const uint32_t* Afh = g_afh + (size_t)blockIdx.x * 8192;
  const uint32_t* Afl = g_afl + (size_t)blockIdx.x * 8192;
  constexpr int WNT = NT / 2;

  const int mw = wid & 3;
  const int nw = wid >> 2;
  float c[2][WNT][4];
#pragma unroll
  for (int mi = 0; mi < 2; mi++)
#pragma unroll
    for (int nt = 0; nt < WNT; nt++)
#pragma unroll
      for (int q = 0; q < 4; q++) c[mi][nt][q] = 0.f;

#pragma unroll
  for (int kt = 0; kt < 8; kt++) {
    uint32_t ah[2][4], al_[2][4];
#pragma unroll
    for (int mi = 0; mi < 2; mi++) {
      int slot = A_FRAG(mw * 2 + mi, kt, lane, 0);
      *(uint4*)ah[mi]  = __ldg((const uint4*)&Afh[slot]);
      *(uint4*)al_[mi] = __ldg((const uint4*)&Afl[slot]);
    }
#pragma unroll
    for (int nh = 0; nh < WNT / 4; nh++) {
      uint32_t bh[4][2], bl_[4][2];
#pragma unroll
      for (int nt = 0; nt < 4; nt++) {
        int ntile = nw * WNT + nh * 4 + nt;
        int slot = ((kt * NT + ntile) * 32 + lane) * 2;
        *(uint2*)bh[nt]  = __ldg((const uint2*)&Bh[slot]);
        *(uint2*)bl_[nt] = __ldg((const uint2*)&Bl[slot]);
      }
#pragma unroll
      for (int mi = 0; mi < 2; mi++)
#pragma unroll
        for (int nt = 0; nt < 4; nt++) {
          float* cc = c[mi][nh * 4 + nt];
          mma_bf16(cc, ah[mi], bh[nt]);
          mma_bf16(cc, ah[mi], bl_[nt]);
          mma_bf16(cc, al_[mi], bh[nt]);
        }
    }
  }

#pragma unroll
  for (int mi = 0; mi < 2; mi++) {
    int r0 = bm + mw * 32 + mi * 16 + (lane >> 2);
    int r1 = r0 + 8;
    float s0 = (r0 < M) ? g_dinv[r0] : 0.f;
    float s1 = (r1 < M) ? g_dinv[r1] : 0.f;
#pragma unroll
    for (int nt = 0; nt < WNT; nt++) {
      int col = (nw * WNT + nt) * 8 + (lane & 3) * 2;
      if (col >= DOUT) continue;
      if (r0 < M)
        *(float2*)(g_g + (size_t)r0 * DOUT + col) =
            make_float2(c[mi][nt][0] * s0, c[mi][nt][1] * s0);
      if (r1 < M)
        *(float2*)(g_g + (size_t)r1 * DOUT + col) =
            make_float2(c[mi][nt][2] * s1, c[mi][nt][3] * s1);
    }
  }
}

// ---------------- CSR gather -> next layer's A fragments ----------------
// warp per node; lane owns cols 4*lane..4*lane+3 (k pairs 2*lane, 2*lane+1).
// h = relu(acc*dinv + bias) computed in fp32, split hi/lo, stored in frag
// layout (identical math to the old in-GEMM convert).

__global__ void k_gather_frag(const float* __restrict__ bias, int n) {
  int w    = (blockIdx.x * blockDim.x + threadIdx.x) >> 5;
  int lane = threadIdx.x & 31;
  if (w >= n) return;
  int beg = __ldg(g_rowptr + w);
  int end = __ldg(g_rowptr + w + 1);
  float4 acc = *(const float4*)(g_g + (size_t)w * 128 + lane * 4);
  int e = beg;
  for (; e + 4 <= end; e += 4) {
    int s0 = __ldg(g_eidx + e);
    int s1 = __ldg(g_eidx + e + 1);
    int s2 = __ldg(g_eidx + e + 2);
    int s3 = __ldg(g_eidx + e + 3);
    float4 v0 = __ldg((const float4*)(g_g + (size_t)s0 * 128 + lane * 4));
    float4 v1 = __ldg((const float4*)(g_g + (size_t)s1 * 128 + lane * 4));
    float4 v2 = __ldg((const float4*)(g_g + (size_t)s2 * 128 + lane * 4));
    float4 v3 = __ldg((const float4*)(g_g + (size_t)s3 * 128 + lane * 4));
    acc.x += v0.x; acc.y += v0.y; acc.z += v0.z; acc.w += v0.w;
    acc.x += v1.x; acc.y += v1.y; acc.z += v1.z; acc.w += v1.w;
    acc.x += v2.x; acc.y += v2.y; acc.z += v2.z; acc.w += v2.w;
    acc.x += v3.x; acc.y += v3.y; acc.z += v3.z; acc.w += v3.w;
  }
  for (; e < end; e++) {
    int s = __ldg(g_eidx + e);
    float4 v = __ldg((const float4*)(g_g + (size_t)s * 128 + lane * 4));
    acc.x += v.x; acc.y += v.y; acc.z += v.z; acc.w += v.w;
  }
  // finalize: h = relu(acc*dinv + bias)
  float sc = g_dinv[w];
  float4 b = *(const float4*)(bias + lane * 4);
  float h0 = fmaxf(acc.x * sc + b.x, 0.f);
  float h1 = fmaxf(acc.y * sc + b.y, 0.f);
  float h2 = fmaxf(acc.z * sc + b.z, 0.f);
  float h3 = fmaxf(acc.w * sc + b.w, 0.f);
  // split + fragment store
  __nv_bfloat16 p0 = __float2bfloat16(h0), p1 = __float2bfloat16(h1);
  __nv_bfloat16 p2 = __float2bfloat16(h2), p3 = __float2bfloat16(h3);
  float q0 = h0 - __bfloat162float(p0), q1 = h1 - __bfloat162float(p1);
  float q2 = h2 - __bfloat162float(p2), q3 = h3 - __bfloat162float(p3);
  int block = w >> 7, mloc = w & 127;
  int r = mloc & 15, mt = mloc >> 4;
  int kt = lane >> 2;
  int fl0 = (r & 7) * 4 + ((2 * lane) & 3);
  int j = (r >> 3) + ((lane >> 1) & 1) * 2;
  size_t slot0 = (size_t)block * 8192 + A_FRAG(mt, kt, fl0, j);
  g_afh[slot0]     = pack_bf16(__bfloat162float(p0), __bfloat162float(p1));
  g_afh[slot0 + 4] = pack_bf16(__bfloat162float(p2), __bfloat162float(p3));
  g_afl[slot0]     = pack_bf16(q0, q1);
  g_afl[slot0 + 4] = pack_bf16(q2, q3);
}

// last layer (D=40): gather + finalize fused, half-warp per node -> d_out.
__global__ void k_gather_out(const float* __restrict__ bias,
                             float* __restrict__ out, int n, int D) {
  int t    = blockIdx.x * blockDim.x + threadIdx.x;
  int node = t >> 4;
  int lane = t & 15;
  if (node >= n) return;
  int c = lane * 4;
  if (c >= D) return;
  int beg = __ldg(g_rowptr + node);
  int end = __ldg(g_rowptr + node + 1);
  float4 acc = *(const float4*)(g_g + (size_t)node * D + c);
  int e = beg;
  for (; e + 4 <= end; e += 4) {
    int s0 = __ldg(g_eidx + e);
    int s1 = __ldg(g_eidx + e + 1);
    int s2 = __ldg(g_eidx + e + 2);
    int s3 = __ldg(g_eidx + e + 3);
    float4 v0 = __ldg((const float4*)(g_g + (size_t)s0 * D + c));
    float4 v1 = __ldg((const float4*)(g_g + (size_t)s1 * D + c));
    float4 v2 = __ldg((const float4*)(g_g + (size_t)s2 * D + c));
    float4 v3 = __ldg((const float4*)(g_g + (size_t)s3 * D + c));
    acc.x += v0.x; acc.y += v0.y; acc.z += v0.z; acc.w += v0.w;
    acc.x += v1.x; acc.y += v1.y; acc.z += v1.z; acc.w += v1.w;
    acc.x += v2.x; acc.y += v2.y; acc.z += v2.z; acc.w += v2.w;
    acc.x += v3.x; acc.y += v3.y; acc.z += v3.z; acc.w += v3.w;
  }
  for (; e < end; e++) {
    int s = __ldg(g_eidx + e);
    float4 v = __ldg((const float4*)(g_g + (size_t)s * D + c));
    acc.x += v.x; acc.y += v.y; acc.z += v.z; acc.w += v.w;
  }
  float sc = g_dinv[node];
  float4 b = *(const float4*)(bias + c);
  acc.x = acc.x * sc + b.x;
  acc.y = acc.y * sc + b.y;
  acc.z = acc.z * sc + b.z;
  acc.w = acc.w * sc + b.w;
  *(float4*)(out + (size_t)node * D + c) = acc;
}

// ---------------- host launcher ----------------

extern "C" void kernel_launch(void* const* d_in, const int* in_sizes, int n_in,
                              void* d_out, int out_size) {
  const float* x  = (const float*)d_in[0];
  const int*   ei = (const int*)d_in[1];
  const float* W[4] = {(const float*)d_in[2], (const float*)d_in[4],
                       (const float*)d_in[6], (const float*)d_in[8]};
  const float* b[4] = {(const float*)d_in[3], (const float*)d_in[5],
                       (const float*)d_in[7], (const float*)d_in[9]};

  int M = in_sizes[0] / FD;  // 100000
  int E = in_sizes[1] / 2;   // 500000
  const int* src = ei;
  const int* dst = ei + E;

  uint32_t *wfh, *wfl, *w3h, *w3l;
  cudaGetSymbolAddress((void**)&wfh, g_wfh);
  cudaGetSymbolAddress((void**)&wfl, g_wfl);
  cudaGetSymbolAddress((void**)&w3h, g_w3h);
  cudaGetSymbolAddress((void**)&w3l, g_w3l);

  const int SMEM = 65536;
  cudaFuncSetAttribute((const void*)k_gemm_l0,
                       cudaFuncAttributeMaxDynamicSharedMemorySize, SMEM);

  int nscan = (M + SCAN_B - 1) / SCAN_B;  // 196
  int GB = (M + 127) / 128;               // 782
  int gatherB = (M * 32 + 255) / 256;     // 12500

  // degree + W prep
  k_zero_cnt<<<(M + 255) / 256, 256>>>(M);
  k_count<<<(E + 255) / 256, 256>>>(dst, E);
  k_wprep_all<<<dim3(32, 4), 256>>>(W[0], W[1], W[2], W[3]);
  // scan prefix (scan1 also computes dinv)
  k_scan1<<<nscan, SCAN_B>>>(M);
  k_scan2<<<1, 256>>>(nscan);
  // layer-0 GEMM as 6th launch (needs only dinv + W0 frags)
  k_gemm_l0<<<GB, 256, SMEM>>>(x, wfh, wfl, M);
  // finish CSR
  k_scan3<<<nscan, SCAN_B>>>(M);
  k_fill<<<(E + 255) / 256, 256>>>(src, dst, E);

  // layer 0 aggregate -> A frags for layer 1
  k_gather_frag<<<gatherB, 256>>>(b[0], M);
  // layers 1-2: frag GEMM + gather
  k_gemm_frag<16, 128><<<GB, 256>>>(wfh + 8192, wfl + 8192, M);
  k_gather_frag<<<gatherB, 256>>>(b[1], M);
  k_gemm_frag<16, 128><<<GB, 256>>>(wfh + 16384, wfl + 16384, M);
  k_gather_frag<<<gatherB, 256>>>(b[2], M);
  // layer 3: D=40 frag GEMM + fused gather/finalize -> d_out
  k_gemm_frag<8, 40><<<GB, 256>>>(w3h, w3l, M);
  k_gather_out<<<(M * 16 + 255) / 256, 256>>>(b[3], (float*)d_out, M, 40);
}